// round 7
// baseline (speedup 1.0000x reference)
#include <cuda_runtime.h>
#include <cuda_bf16.h>
#include <cstdint>
#include <math.h>

#define GFD   4096
#define DH    1024
#define BATCH 32
#define TK    196
#define BT    (BATCH * TK)   // 6272

// Output layout in d_out (float): c_img[32,1024] | coverage_new[32,196,1] | alpha[32,196,1]
#define OUT_C      0
#define OUT_COV    (BATCH * DH)
#define OUT_ALPHA  (BATCH * DH + BT)

// ============================ scratch (__device__ globals) ============================
__device__ __align__(1024) __nv_bfloat16 g_WgH[GFD * GFD];
__device__ __align__(1024) __nv_bfloat16 g_WgL[GFD * GFD];
__device__ __align__(1024) __nv_bfloat16 g_gfH[BT * GFD];
__device__ __align__(1024) __nv_bfloat16 g_gfL[BT * GFD];
__device__ __align__(1024) __nv_bfloat16 g_GsTH[DH * GFD];   // Gs^T  [DH, GFD]
__device__ __align__(1024) __nv_bfloat16 g_GsTL[DH * GFD];
__device__ __align__(1024) float         g_W2[GFD * DH];     // Wg@Gs [GFD, DH]
__device__ __align__(1024) __nv_bfloat16 g_W2TH[DH * GFD];   // W2^T  [DH, GFD]
__device__ __align__(1024) __nv_bfloat16 g_W2TL[DH * GFD];
__device__ __align__(1024) __nv_bfloat16 g_WgsTH[DH * DH];   // Wgs^T [DH, DH]
__device__ __align__(1024) __nv_bfloat16 g_WgsTL[DH * DH];
__device__ __align__(1024) float         g_gstar[BT * DH];
__device__ __align__(1024) __nv_bfloat16 g_gsH[BT * DH];
__device__ __align__(1024) __nv_bfloat16 g_gsL[BT * DH];
__device__ float g_b2[DH];
__device__ float g_dec[BATCH * DH];
__device__ float g_scores[BT];
__device__ float g_alpha[BT];

// ============================ helpers ============================
__device__ __forceinline__ uint32_t smem_u32(const void* p) {
    uint32_t a;
    asm("{ .reg .u64 t; cvta.to.shared.u64 t, %1; cvt.u32.u64 %0, t; }" : "=r"(a) : "l"(p));
    return a;
}
__device__ __forceinline__ void ldsm4(uint32_t* r, uint32_t addr) {
    asm volatile("ldmatrix.sync.aligned.m8n8.x4.shared.b16 {%0,%1,%2,%3}, [%4];"
                 : "=r"(r[0]), "=r"(r[1]), "=r"(r[2]), "=r"(r[3]) : "r"(addr));
}
__device__ __forceinline__ void mma16816(float* c, const uint32_t* a, const uint32_t* b) {
    asm volatile("mma.sync.aligned.m16n8k16.row.col.f32.bf16.bf16.f32 "
                 "{%0,%1,%2,%3}, {%4,%5,%6,%7}, {%8,%9}, {%0,%1,%2,%3};"
                 : "+f"(c[0]), "+f"(c[1]), "+f"(c[2]), "+f"(c[3])
                 : "r"(a[0]), "r"(a[1]), "r"(a[2]), "r"(a[3]), "r"(b[0]), "r"(b[1]));
}
__device__ __forceinline__ uint32_t swz(uint32_t off) {   // SW128: bits[6:4] ^= bits[9:7]
    return off ^ ((off >> 3) & 0x70);
}

// ============================ split-bf16 mma.sync GEMM ============================
// C[M,N] = Ah@Bh^T + Ah@Bl^T + Al@Bh^T, fp32 accum. A:[M,K] row-major, B:[N,K] row-major.
// CTA: 128 threads (4 warps, 2x2), CTA tile 128x64, K-tile 64, double-buffered cp.async.
// 2 CTAs/SM so one CTA's MMAs cover the other's barriers/loads/epilogue.
#define KTILE     64
#define A_TILE_B  16384                 // 128x64 bf16
#define B_TILE_B  8192                  // 64x64 bf16
#define STG_B     (2 * A_TILE_B + 2 * B_TILE_B)   // 48 KB
#define SM_AH(s)  ((s) * STG_B)
#define SM_AL(s)  (SM_AH(s) + A_TILE_B)
#define SM_BH(s)  (SM_AH(s) + 2 * A_TILE_B)
#define SM_BL(s)  (SM_AH(s) + 2 * A_TILE_B + B_TILE_B)
#define GEMM_SMEM (2 * STG_B)           // 96 KB

__device__ __forceinline__ void issue_stage(
    uint32_t sb, int s, int kt,
    const __nv_bfloat16* __restrict__ Ah, const __nv_bfloat16* __restrict__ Al,
    const __nv_bfloat16* __restrict__ Bh, const __nv_bfloat16* __restrict__ Bl,
    int K, int bm, int bn, int tid)
{
    const int k0 = kt * KTILE;
#pragma unroll
    for (int i = 0; i < 8; i++) {        // A: 128 rows x 8 cols(16B)
        int idx = tid + i * 128;
        int r = idx >> 3, c = idx & 7;
        uint32_t so = swz((uint32_t)(r * 128 + c * 16));
        size_t go = (size_t)(bm + r) * K + k0 + c * 8;
        asm volatile("cp.async.cg.shared.global [%0], [%1], 16;" :: "r"(sb + SM_AH(s) + so), "l"(Ah + go) : "memory");
        asm volatile("cp.async.cg.shared.global [%0], [%1], 16;" :: "r"(sb + SM_AL(s) + so), "l"(Al + go) : "memory");
    }
#pragma unroll
    for (int i = 0; i < 4; i++) {        // B: 64 rows x 8 cols(16B)
        int idx = tid + i * 128;
        int r = idx >> 3, c = idx & 7;
        uint32_t so = swz((uint32_t)(r * 128 + c * 16));
        size_t go = (size_t)(bn + r) * K + k0 + c * 8;
        asm volatile("cp.async.cg.shared.global [%0], [%1], 16;" :: "r"(sb + SM_BH(s) + so), "l"(Bh + go) : "memory");
        asm volatile("cp.async.cg.shared.global [%0], [%1], 16;" :: "r"(sb + SM_BL(s) + so), "l"(Bl + go) : "memory");
    }
    asm volatile("cp.async.commit_group;" ::: "memory");
}

// mode 0: outF = D                                   (W2)
// mode 1: outF = D + bias; emit bf16 hi/lo           (g_star)
// mode 2: scores[m] += sum_n tanh(D + dec + cov)*v   (fused attention scores)
__global__ void __launch_bounds__(128, 2) gemm_mma(
    const __nv_bfloat16* __restrict__ Ah, const __nv_bfloat16* __restrict__ Al,
    const __nv_bfloat16* __restrict__ Bh, const __nv_bfloat16* __restrict__ Bl,
    int K, int KT, int mode,
    float* __restrict__ outF, const float* __restrict__ bias,
    __nv_bfloat16* __restrict__ outH, __nv_bfloat16* __restrict__ outL,
    const float* __restrict__ dec, const float* __restrict__ cov,
    const float* __restrict__ v, float* __restrict__ scores)
{
    extern __shared__ char smem[];
    const uint32_t sb  = smem_u32(smem);
    const int tid  = threadIdx.x;
    const int wid  = tid >> 5, lane = tid & 31;
    const int wm   = wid & 1,  wn   = wid >> 1;     // warp grid 2(m) x 2(n)
    const int bm   = blockIdx.y * 128, bn = blockIdx.x * 64;

    float acc[4][4][4];
#pragma unroll
    for (int a = 0; a < 4; a++)
#pragma unroll
        for (int b = 0; b < 4; b++)
#pragma unroll
            for (int c = 0; c < 4; c++) acc[a][b][c] = 0.f;

    // per-lane ldmatrix offsets (within-tile)
    const uint32_t a_row  = (uint32_t)(wm * 64 + (lane & 15));                         // + mi*16
    const uint32_t a_kofs = (uint32_t)(((lane >> 4) & 1) * 16);                        // + kk*32
    const uint32_t b_row  = (uint32_t)(wn * 32 + (lane & 7) + ((lane >> 4) & 1) * 8);  // + nq*16
    const uint32_t b_kofs = (uint32_t)(((lane >> 3) & 1) * 16);                        // + kk*32

    issue_stage(sb, 0, 0, Ah, Al, Bh, Bl, K, bm, bn, tid);

    for (int kt = 0; kt < KT; kt++) {
        const int s = kt & 1;
        if (kt + 1 < KT) {
            issue_stage(sb, s ^ 1, kt + 1, Ah, Al, Bh, Bl, K, bm, bn, tid);
            asm volatile("cp.async.wait_group 1;" ::: "memory");
        } else {
            asm volatile("cp.async.wait_group 0;" ::: "memory");
        }
        __syncthreads();

        const uint32_t aH = sb + SM_AH(s), aL = sb + SM_AL(s);
        const uint32_t bH = sb + SM_BH(s), bL = sb + SM_BL(s);
#pragma unroll
        for (int kk = 0; kk < 4; kk++) {
            uint32_t fAh[4][4], fAl[4][4], fBh[2][4], fBl[2][4];
            // ---- pass 1: Ah x Bh (16 independent accumulators) ----
#pragma unroll
            for (int mi = 0; mi < 4; mi++) {
                uint32_t off = swz((a_row + mi * 16) * 128 + kk * 32 + a_kofs);
                ldsm4(fAh[mi], aH + off);
            }
#pragma unroll
            for (int nq = 0; nq < 2; nq++) {
                uint32_t off = swz((b_row + nq * 16) * 128 + kk * 32 + b_kofs);
                ldsm4(fBh[nq], bH + off);
            }
#pragma unroll
            for (int mi = 0; mi < 4; mi++)
#pragma unroll
                for (int nt = 0; nt < 4; nt++)
                    mma16816(acc[mi][nt], fAh[mi], &fBh[nt >> 1][(nt & 1) * 2]);

            // ---- pass 2: Ah x Bl ----
#pragma unroll
            for (int nq = 0; nq < 2; nq++) {
                uint32_t off = swz((b_row + nq * 16) * 128 + kk * 32 + b_kofs);
                ldsm4(fBl[nq], bL + off);
            }
#pragma unroll
            for (int mi = 0; mi < 4; mi++)
#pragma unroll
                for (int nt = 0; nt < 4; nt++)
                    mma16816(acc[mi][nt], fAh[mi], &fBl[nt >> 1][(nt & 1) * 2]);

            // ---- pass 3: Al x Bh ----
#pragma unroll
            for (int mi = 0; mi < 4; mi++) {
                uint32_t off = swz((a_row + mi * 16) * 128 + kk * 32 + a_kofs);
                ldsm4(fAl[mi], aL + off);
            }
#pragma unroll
            for (int mi = 0; mi < 4; mi++)
#pragma unroll
                for (int nt = 0; nt < 4; nt++)
                    mma16816(acc[mi][nt], fAl[mi], &fBh[nt >> 1][(nt & 1) * 2]);
        }
        __syncthreads();
    }

    // ---------------- epilogue (register accumulators, vectorized stores) ----------------
    const int g = lane >> 2, tig = lane & 3;
#pragma unroll
    for (int mi = 0; mi < 4; mi++) {
#pragma unroll
        for (int h = 0; h < 2; h++) {
            const int m = bm + wm * 64 + mi * 16 + g + h * 8;
            float rsum = 0.f, cv = 0.f;
            int bofs = 0;
            if (mode == 2) { cv = cov[m]; bofs = (m / TK) * DH; }
#pragma unroll
            for (int nt = 0; nt < 4; nt++) {
                const int n = bn + wn * 32 + nt * 8 + 2 * tig;
                float x0 = acc[mi][nt][h * 2 + 0];
                float x1 = acc[mi][nt][h * 2 + 1];
                if (mode == 0) {
                    *(float2*)&outF[(size_t)m * DH + n] = make_float2(x0, x1);
                } else if (mode == 1) {
                    x0 += bias[n];  x1 += bias[n + 1];
                    *(float2*)&outF[(size_t)m * DH + n] = make_float2(x0, x1);
                    __nv_bfloat16 h0 = __float2bfloat16(x0), h1 = __float2bfloat16(x1);
                    *(__nv_bfloat162*)&outH[(size_t)m * DH + n] = __halves2bfloat162(h0, h1);
                    *(__nv_bfloat162*)&outL[(size_t)m * DH + n] = __halves2bfloat162(
                        __float2bfloat16(x0 - __bfloat162float(h0)),
                        __float2bfloat16(x1 - __bfloat162float(h1)));
                } else {
                    rsum += tanhf(x0 + dec[bofs + n] + cv) * v[n];
                    rsum += tanhf(x1 + dec[bofs + n + 1] + cv) * v[n + 1];
                }
            }
            if (mode == 2) {
                rsum += __shfl_xor_sync(0xffffffffu, rsum, 1);
                rsum += __shfl_xor_sync(0xffffffffu, rsum, 2);
                if (tig == 0) atomicAdd(&scores[m], rsum);
            }
        }
    }
}

// ============================ conversion kernels ============================
__global__ void __launch_bounds__(256) csplit(
    const float4* __restrict__ in, __nv_bfloat162* __restrict__ oh,
    __nv_bfloat162* __restrict__ ol, int n4)
{
    int i = blockIdx.x * 256 + threadIdx.x;
    if (i >= n4) return;
    float4 x = in[i];
    __nv_bfloat16 h0 = __float2bfloat16(x.x), h1 = __float2bfloat16(x.y);
    __nv_bfloat16 h2 = __float2bfloat16(x.z), h3 = __float2bfloat16(x.w);
    oh[2 * i]     = __halves2bfloat162(h0, h1);
    oh[2 * i + 1] = __halves2bfloat162(h2, h3);
    ol[2 * i]     = __halves2bfloat162(__float2bfloat16(x.x - __bfloat162float(h0)),
                                       __float2bfloat16(x.y - __bfloat162float(h1)));
    ol[2 * i + 1] = __halves2bfloat162(__float2bfloat16(x.z - __bfloat162float(h2)),
                                       __float2bfloat16(x.w - __bfloat162float(h3)));
}

// out[C,R] = split(in[R,C]^T)
__global__ void __launch_bounds__(256) tconv(
    const float* __restrict__ in, __nv_bfloat16* __restrict__ oh,
    __nv_bfloat16* __restrict__ ol, int R, int C)
{
    __shared__ float t[32][33];
    const int bx = blockIdx.x * 32, by = blockIdx.y * 32;
    const int x = threadIdx.x & 31, y = threadIdx.x >> 5;
#pragma unroll
    for (int i = 0; i < 32; i += 8)
        t[y + i][x] = in[(size_t)(by + y + i) * C + bx + x];
    __syncthreads();
#pragma unroll
    for (int i = 0; i < 32; i += 8) {
        float val = t[x][y + i];
        __nv_bfloat16 h = __float2bfloat16(val);
        size_t o = (size_t)(bx + y + i) * R + by + x;
        oh[o] = h;
        ol[o] = __float2bfloat16(val - __bfloat162float(h));
    }
}

// ============================ small kernels ============================
// b2 += partial(bg @ Gs) over K-chunk; chunk 0 also adds bgs. b2 must be pre-zeroed.
__global__ void __launch_bounds__(256) b2_kernel(
    const float* __restrict__ bg, const float* __restrict__ Gs,
    const float* __restrict__ bgs, float* __restrict__ b2)
{
    const int j  = blockIdx.x * 256 + threadIdx.x;   // 0..DH-1 (grid.x = 4)
    const int k0 = blockIdx.y * 512;                 // grid.y = 8
    float s = 0.f;
#pragma unroll 8
    for (int i = 0; i < 512; i++)
        s += bg[k0 + i] * Gs[(size_t)(k0 + i) * DH + j];
    if (blockIdx.y == 0) s += bgs[j];
    atomicAdd(&b2[j], s);
}

__global__ void __launch_bounds__(256) dec_kernel(
    const float* __restrict__ s_t_hat, const float* __restrict__ Wdec,
    const float* __restrict__ bdec, float* __restrict__ dec)
{
    const int idx = blockIdx.x * 256 + threadIdx.x;
    const int b = idx >> 10, j = idx & (DH - 1);
    float s = bdec[j];
#pragma unroll 8
    for (int k = 0; k < DH; k++) s += s_t_hat[b * DH + k] * Wdec[(size_t)k * DH + j];
    dec[idx] = s;
}

__global__ void __launch_bounds__(256) softmax_kernel(
    const float* __restrict__ scores, const float* __restrict__ cov,
    float* __restrict__ alpha, float* __restrict__ out)
{
    const int b = blockIdx.x, t = threadIdx.x;
    __shared__ float red[8];
    __shared__ float smax, ssum;
    float sv = (t < TK) ? scores[b * TK + t] : -3.4e38f;

    float m = sv;
#pragma unroll
    for (int o = 16; o > 0; o >>= 1) m = fmaxf(m, __shfl_xor_sync(0xffffffffu, m, o));
    if ((t & 31) == 0) red[t >> 5] = m;
    __syncthreads();
    if (t < 8) {
        m = red[t];
#pragma unroll
        for (int o = 4; o > 0; o >>= 1) m = fmaxf(m, __shfl_xor_sync(0xffu, m, o));
        if (t == 0) smax = m;
    }
    __syncthreads();

    float e = (t < TK) ? expf(sv - smax) : 0.f;
    float su = e;
#pragma unroll
    for (int o = 16; o > 0; o >>= 1) su += __shfl_xor_sync(0xffffffffu, su, o);
    if ((t & 31) == 0) red[t >> 5] = su;
    __syncthreads();
    if (t < 8) {
        su = red[t];
#pragma unroll
        for (int o = 4; o > 0; o >>= 1) su += __shfl_xor_sync(0xffu, su, o);
        if (t == 0) ssum = su;
    }
    __syncthreads();

    if (t < TK) {
        const float a = e / ssum;
        alpha[b * TK + t] = a;
        out[OUT_ALPHA + b * TK + t] = a;
        out[OUT_COV + b * TK + t] = cov[b * TK + t] + a;
    }
}

__global__ void __launch_bounds__(256) cimg_kernel(
    const float* __restrict__ gstar, const float* __restrict__ alpha,
    float* __restrict__ out)
{
    const int b = blockIdx.y;
    const int d = blockIdx.x * 256 + threadIdx.x;
    __shared__ float sal[TK];
    if (threadIdx.x < TK) sal[threadIdx.x] = alpha[b * TK + threadIdx.x];
    __syncthreads();
    float s = 0.f;
#pragma unroll 4
    for (int t = 0; t < TK; t++)
        s += sal[t] * gstar[((size_t)(b * TK + t)) * DH + d];
    out[OUT_C + b * DH + d] = s;
}

// ============================ launch ============================
extern "C" void kernel_launch(void* const* d_in, const int* in_sizes, int n_in,
                              void* d_out, int out_size)
{
    const float* gf   = (const float*)d_in[0];
    const float* sth  = (const float*)d_in[1];
    const float* cov  = (const float*)d_in[2];
    const float* Wg   = (const float*)d_in[3];
    const float* bg   = (const float*)d_in[4];
    const float* Gs   = (const float*)d_in[5];
    const float* bgs  = (const float*)d_in[6];
    const float* Wgs  = (const float*)d_in[7];
    const float* Wdec = (const float*)d_in[8];
    const float* bdec = (const float*)d_in[9];
    const float* v    = (const float*)d_in[10];
    float* out = (float*)d_out;

    __nv_bfloat16 *WgH, *WgL, *gfH, *gfL, *GsTH, *GsTL, *W2TH, *W2TL, *WgsTH, *WgsTL, *gsH, *gsL;
    float *W2p, *gstarp, *b2p, *decp, *scoresp, *alphap;
    cudaGetSymbolAddress((void**)&WgH, g_WgH);     cudaGetSymbolAddress((void**)&WgL, g_WgL);
    cudaGetSymbolAddress((void**)&gfH, g_gfH);     cudaGetSymbolAddress((void**)&gfL, g_gfL);
    cudaGetSymbolAddress((void**)&GsTH, g_GsTH);   cudaGetSymbolAddress((void**)&GsTL, g_GsTL);
    cudaGetSymbolAddress((void**)&W2p, g_W2);
    cudaGetSymbolAddress((void**)&W2TH, g_W2TH);   cudaGetSymbolAddress((void**)&W2TL, g_W2TL);
    cudaGetSymbolAddress((void**)&WgsTH, g_WgsTH); cudaGetSymbolAddress((void**)&WgsTL, g_WgsTL);
    cudaGetSymbolAddress((void**)&gstarp, g_gstar);
    cudaGetSymbolAddress((void**)&gsH, g_gsH);     cudaGetSymbolAddress((void**)&gsL, g_gsL);
    cudaGetSymbolAddress((void**)&b2p, g_b2);      cudaGetSymbolAddress((void**)&decp, g_dec);
    cudaGetSymbolAddress((void**)&scoresp, g_scores);
    cudaGetSymbolAddress((void**)&alphap, g_alpha);

    cudaFuncSetAttribute(gemm_mma, cudaFuncAttributeMaxDynamicSharedMemorySize, GEMM_SMEM);

    // Side stream + fork/join events (created once; reused every call — resources, not work)
    static cudaStream_t sideS = nullptr;
    static cudaEvent_t evFork = nullptr, evJoin = nullptr;
    if (sideS == nullptr) {
        cudaStreamCreateWithFlags(&sideS, cudaStreamNonBlocking);
        cudaEventCreateWithFlags(&evFork, cudaEventDisableTiming);
        cudaEventCreateWithFlags(&evJoin, cudaEventDisableTiming);
    }

    // ---- fork ----
    cudaEventRecord(evFork, 0);
    cudaStreamWaitEvent(sideS, evFork, 0);

    // ---- side stream: everything GEMM1 does NOT depend on ----
    cudaMemsetAsync(b2p, 0, DH * sizeof(float), sideS);
    cudaMemsetAsync(scoresp, 0, BT * sizeof(float), sideS);
    csplit<<<(BT * GFD / 4 + 255) / 256, 256, 0, sideS>>>((const float4*)gf,
        (__nv_bfloat162*)gfH, (__nv_bfloat162*)gfL, BT * GFD / 4);
    {   dim3 g(DH / 256, 8);  b2_kernel<<<g, 256, 0, sideS>>>(bg, Gs, bgs, b2p); }
    dec_kernel<<<(BATCH * DH) / 256, 256, 0, sideS>>>(sth, Wdec, bdec, decp);
    {   dim3 g(DH / 32, DH / 32);  tconv<<<g, 256, 0, sideS>>>(Wgs, WgsTH, WgsTL, DH, DH); }
    cudaEventRecord(evJoin, sideS);

    // ---- main stream: GEMM1 chain ----
    csplit<<<(GFD * GFD / 4 + 255) / 256, 256>>>((const float4*)Wg,
        (__nv_bfloat162*)WgH, (__nv_bfloat162*)WgL, GFD * GFD / 4);
    {   dim3 g(DH / 32, GFD / 32);  tconv<<<g, 256>>>(Gs, GsTH, GsTL, GFD, DH); }
    // GEMM1: W2 = Wg @ Gs   [4096,1024], K=4096
    {
        dim3 grid(DH / 64, GFD / 128);
        gemm_mma<<<grid, 128, GEMM_SMEM>>>(WgH, WgL, GsTH, GsTL, GFD, GFD / KTILE, 0,
            W2p, nullptr, nullptr, nullptr, nullptr, nullptr, nullptr, nullptr);
    }
    {   dim3 g(DH / 32, GFD / 32);  tconv<<<g, 256>>>(W2p, W2TH, W2TL, GFD, DH); }

    // ---- join ----
    cudaStreamWaitEvent(0, evJoin, 0);

    // GEMM2: g_star = gf @ W2 + b2   [6272,1024], K=4096
    {
        dim3 grid(DH / 64, BT / 128);
        gemm_mma<<<grid, 128, GEMM_SMEM>>>(gfH, gfL, W2TH, W2TL, GFD, GFD / KTILE, 1,
            gstarp, b2p, gsH, gsL, nullptr, nullptr, nullptr, nullptr);
    }
    // GEMM3 (fused): scores = tanh(g_star@Wgs + dec + cov) . v   K=1024
    {
        dim3 grid(DH / 64, BT / 128);
        gemm_mma<<<grid, 128, GEMM_SMEM>>>(gsH, gsL, WgsTH, WgsTL, DH, DH / KTILE, 2,
            nullptr, nullptr, nullptr, nullptr, decp, cov, v, scoresp);
    }
    // softmax + outputs
    softmax_kernel<<<BATCH, 256>>>(scoresp, cov, alphap, out);
    // context vector
    {   dim3 grid(DH / 256, BATCH);  cimg_kernel<<<grid, 256>>>(gstarp, alphap, out); }
}

// round 8
// speedup vs baseline: 1.5302x; 1.5302x over previous
#include <cuda_runtime.h>
#include <cuda_bf16.h>
#include <cuda_fp16.h>
#include <cstdint>
#include <math.h>

#define GFD   4096
#define DH    1024
#define BATCH 32
#define TK    196
#define BT    (BATCH * TK)   // 6272

// Output layout in d_out (float): c_img[32,1024] | coverage_new[32,196,1] | alpha[32,196,1]
#define OUT_C      0
#define OUT_COV    (BATCH * DH)
#define OUT_ALPHA  (BATCH * DH + BT)

// ============================ scratch (__device__ globals) ============================
__device__ __align__(1024) __nv_bfloat16 g_WgH[GFD * GFD];   // Wg bf16 hi
__device__ __align__(1024) __nv_bfloat16 g_WgL[GFD * GFD];   // Wg bf16 lo
__device__ __align__(1024) __nv_bfloat16 g_GsTH[DH * GFD];   // Gs^T bf16 hi [DH, GFD]
__device__ __align__(1024) __nv_bfloat16 g_GsTL[DH * GFD];
__device__ __align__(1024) __half        g_W2TF[DH * GFD];   // W2^T fp16 single [DH, GFD]
__device__ __align__(1024) __half        g_gfH[BT * GFD];    // gf fp16 hi
__device__ __align__(1024) __half        g_gfL[BT * GFD];    // gf fp16 lo
__device__ __align__(1024) __nv_bfloat16 g_WgsTH[DH * DH];   // Wgs^T bf16 hi [DH, DH]
__device__ __align__(1024) __nv_bfloat16 g_WgsTL[DH * DH];
__device__ __align__(1024) float         g_gstar[BT * DH];
__device__ __align__(1024) __nv_bfloat16 g_gsH[BT * DH];     // g_star bf16 hi
__device__ __align__(1024) __nv_bfloat16 g_gsL[BT * DH];
__device__ float g_b2[DH];
__device__ float g_dec[BATCH * DH];
__device__ float g_scores[BT];
__device__ float g_alpha[BT];

// ============================ helpers ============================
__device__ __forceinline__ uint32_t smem_u32(const void* p) {
    uint32_t a;
    asm("{ .reg .u64 t; cvta.to.shared.u64 t, %1; cvt.u32.u64 %0, t; }" : "=r"(a) : "l"(p));
    return a;
}
__device__ __forceinline__ void ldsm4(uint32_t* r, uint32_t addr) {
    asm volatile("ldmatrix.sync.aligned.m8n8.x4.shared.b16 {%0,%1,%2,%3}, [%4];"
                 : "=r"(r[0]), "=r"(r[1]), "=r"(r[2]), "=r"(r[3]) : "r"(addr));
}
template<int NPASS>   // 3 => bf16 operands, 2 => fp16 operands
__device__ __forceinline__ void mma_op(float* c, const uint32_t* a, const uint32_t* b) {
    if constexpr (NPASS == 3) {
        asm volatile("mma.sync.aligned.m16n8k16.row.col.f32.bf16.bf16.f32 "
                     "{%0,%1,%2,%3}, {%4,%5,%6,%7}, {%8,%9}, {%0,%1,%2,%3};"
                     : "+f"(c[0]), "+f"(c[1]), "+f"(c[2]), "+f"(c[3])
                     : "r"(a[0]), "r"(a[1]), "r"(a[2]), "r"(a[3]), "r"(b[0]), "r"(b[1]));
    } else {
        asm volatile("mma.sync.aligned.m16n8k16.row.col.f32.f16.f16.f32 "
                     "{%0,%1,%2,%3}, {%4,%5,%6,%7}, {%8,%9}, {%0,%1,%2,%3};"
                     : "+f"(c[0]), "+f"(c[1]), "+f"(c[2]), "+f"(c[3])
                     : "r"(a[0]), "r"(a[1]), "r"(a[2]), "r"(a[3]), "r"(b[0]), "r"(b[1]));
    }
}
__device__ __forceinline__ uint32_t swz(uint32_t off) {   // SW128: bits[6:4] ^= bits[9:7]
    return off ^ ((off >> 3) & 0x70);
}

// ============================ split 16-bit mma.sync GEMM ============================
// NPASS=3 (bf16): C = Ah@Bh^T + Ah@Bl^T + Al@Bh^T
// NPASS=2 (fp16): C = Ah@Bh^T + Al@Bh^T          (Bl unused)
// A:[M,K] row-major 16-bit, B:[N,K] row-major 16-bit, fp32 accum.
// CTA 128 threads (2x2 warps), tile 128x64, K-tile 64, double-buffered cp.async, 2 CTAs/SM.
#define KTILE     64
#define A_TILE_B  16384
#define B_TILE_B  8192
#define STG_B     (2 * A_TILE_B + 2 * B_TILE_B)   // 48 KB
#define SM_AH(s)  ((s) * STG_B)
#define SM_AL(s)  (SM_AH(s) + A_TILE_B)
#define SM_BH(s)  (SM_AH(s) + 2 * A_TILE_B)
#define SM_BL(s)  (SM_AH(s) + 2 * A_TILE_B + B_TILE_B)
#define GEMM_SMEM (2 * STG_B)                     // 96 KB

template<int NPASS>
__device__ __forceinline__ void issue_stage(
    uint32_t sb, int s, int kt,
    const char* Ah, const char* Al, const char* Bh, const char* Bl,
    int K, int bm, int bn, int tid)
{
    const int k0 = kt * KTILE;
#pragma unroll
    for (int i = 0; i < 8; i++) {        // A: 128 rows x 8 cols(16B)
        int idx = tid + i * 128;
        int r = idx >> 3, c = idx & 7;
        uint32_t so = swz((uint32_t)(r * 128 + c * 16));
        size_t go = ((size_t)(bm + r) * K + k0 + c * 8) * 2;
        asm volatile("cp.async.cg.shared.global [%0], [%1], 16;" :: "r"(sb + SM_AH(s) + so), "l"(Ah + go) : "memory");
        asm volatile("cp.async.cg.shared.global [%0], [%1], 16;" :: "r"(sb + SM_AL(s) + so), "l"(Al + go) : "memory");
    }
#pragma unroll
    for (int i = 0; i < 4; i++) {        // B: 64 rows x 8 cols(16B)
        int idx = tid + i * 128;
        int r = idx >> 3, c = idx & 7;
        uint32_t so = swz((uint32_t)(r * 128 + c * 16));
        size_t go = ((size_t)(bn + r) * K + k0 + c * 8) * 2;
        asm volatile("cp.async.cg.shared.global [%0], [%1], 16;" :: "r"(sb + SM_BH(s) + so), "l"(Bh + go) : "memory");
        if constexpr (NPASS == 3) {
            asm volatile("cp.async.cg.shared.global [%0], [%1], 16;" :: "r"(sb + SM_BL(s) + so), "l"(Bl + go) : "memory");
        }
    }
    asm volatile("cp.async.commit_group;" ::: "memory");
}

// mode 3: outF16[m*ldc+n] = D (fp16 single)       (W2^T)
// mode 1: outF = D + bias; emit bf16 hi/lo        (g_star)
// mode 2: scores[m] += sum_n tanh(D + dec + cov)*v
template<int NPASS>
__global__ void __launch_bounds__(128, 2) gemm_mma(
    const void* Ah_, const void* Al_, const void* Bh_, const void* Bl_,
    int K, int KT, int mode, int ldc,
    float* __restrict__ outF, const float* __restrict__ bias,
    __nv_bfloat16* __restrict__ outH, __nv_bfloat16* __restrict__ outL,
    __half* __restrict__ outF16,
    const float* __restrict__ dec, const float* __restrict__ cov,
    const float* __restrict__ v, float* __restrict__ scores)
{
    extern __shared__ char smem[];
    const uint32_t sb  = smem_u32(smem);
    const int tid  = threadIdx.x;
    const int wid  = tid >> 5, lane = tid & 31;
    const int wm   = wid & 1,  wn   = wid >> 1;     // warp grid 2(m) x 2(n)
    const int bm   = blockIdx.y * 128, bn = blockIdx.x * 64;
    const char* Ah = (const char*)Ah_;  const char* Al = (const char*)Al_;
    const char* Bh = (const char*)Bh_;  const char* Bl = (const char*)Bl_;

    float acc[4][4][4];
#pragma unroll
    for (int a = 0; a < 4; a++)
#pragma unroll
        for (int b = 0; b < 4; b++)
#pragma unroll
            for (int c = 0; c < 4; c++) acc[a][b][c] = 0.f;

    // per-lane ldmatrix offsets (within-tile)
    const uint32_t a_row  = (uint32_t)(wm * 64 + (lane & 15));                         // + mi*16
    const uint32_t a_kofs = (uint32_t)(((lane >> 4) & 1) * 16);                        // + kk*32
    const uint32_t b_row  = (uint32_t)(wn * 32 + (lane & 7) + ((lane >> 4) & 1) * 8);  // + nq*16
    const uint32_t b_kofs = (uint32_t)(((lane >> 3) & 1) * 16);                        // + kk*32

    issue_stage<NPASS>(sb, 0, 0, Ah, Al, Bh, Bl, K, bm, bn, tid);

    for (int kt = 0; kt < KT; kt++) {
        const int s = kt & 1;
        if (kt + 1 < KT) {
            issue_stage<NPASS>(sb, s ^ 1, kt + 1, Ah, Al, Bh, Bl, K, bm, bn, tid);
            asm volatile("cp.async.wait_group 1;" ::: "memory");
        } else {
            asm volatile("cp.async.wait_group 0;" ::: "memory");
        }
        __syncthreads();

        const uint32_t aH = sb + SM_AH(s), aL = sb + SM_AL(s);
        const uint32_t bH = sb + SM_BH(s), bL = sb + SM_BL(s);
#pragma unroll
        for (int kk = 0; kk < 4; kk++) {
            uint32_t fAh[4][4], fAl[4][4], fBh[2][4];
            // ---- pass 1: Ah x Bh (16 independent accumulators) ----
#pragma unroll
            for (int mi = 0; mi < 4; mi++) {
                uint32_t off = swz((a_row + mi * 16) * 128 + kk * 32 + a_kofs);
                ldsm4(fAh[mi], aH + off);
            }
#pragma unroll
            for (int nq = 0; nq < 2; nq++) {
                uint32_t off = swz((b_row + nq * 16) * 128 + kk * 32 + b_kofs);
                ldsm4(fBh[nq], bH + off);
            }
#pragma unroll
            for (int mi = 0; mi < 4; mi++)
#pragma unroll
                for (int nt = 0; nt < 4; nt++)
                    mma_op<NPASS>(acc[mi][nt], fAh[mi], &fBh[nt >> 1][(nt & 1) * 2]);

            // ---- pass 2 (bf16 3-pass only): Ah x Bl ----
            if constexpr (NPASS == 3) {
                uint32_t fBl[2][4];
#pragma unroll
                for (int nq = 0; nq < 2; nq++) {
                    uint32_t off = swz((b_row + nq * 16) * 128 + kk * 32 + b_kofs);
                    ldsm4(fBl[nq], bL + off);
                }
#pragma unroll
                for (int mi = 0; mi < 4; mi++)
#pragma unroll
                    for (int nt = 0; nt < 4; nt++)
                        mma_op<NPASS>(acc[mi][nt], fAh[mi], &fBl[nt >> 1][(nt & 1) * 2]);
            }

            // ---- pass 3: Al x Bh ----
#pragma unroll
            for (int mi = 0; mi < 4; mi++) {
                uint32_t off = swz((a_row + mi * 16) * 128 + kk * 32 + a_kofs);
                ldsm4(fAl[mi], aL + off);
            }
#pragma unroll
            for (int mi = 0; mi < 4; mi++)
#pragma unroll
                for (int nt = 0; nt < 4; nt++)
                    mma_op<NPASS>(acc[mi][nt], fAl[mi], &fBh[nt >> 1][(nt & 1) * 2]);
        }
        __syncthreads();
    }

    // ---------------- epilogue ----------------
    const int g = lane >> 2, tig = lane & 3;
#pragma unroll
    for (int mi = 0; mi < 4; mi++) {
#pragma unroll
        for (int h = 0; h < 2; h++) {
            const int m = bm + wm * 64 + mi * 16 + g + h * 8;
            float rsum = 0.f, cv = 0.f;
            int bofs = 0;
            if (mode == 2) { cv = cov[m]; bofs = (m / TK) * DH; }
#pragma unroll
            for (int nt = 0; nt < 4; nt++) {
                const int n = bn + wn * 32 + nt * 8 + 2 * tig;
                float x0 = acc[mi][nt][h * 2 + 0];
                float x1 = acc[mi][nt][h * 2 + 1];
                if (mode == 3) {
                    *(__half2*)&outF16[(size_t)m * ldc + n] = __floats2half2_rn(x0, x1);
                } else if (mode == 1) {
                    x0 += bias[n];  x1 += bias[n + 1];
                    *(float2*)&outF[(size_t)m * ldc + n] = make_float2(x0, x1);
                    __nv_bfloat16 h0 = __float2bfloat16(x0), h1 = __float2bfloat16(x1);
                    *(__nv_bfloat162*)&outH[(size_t)m * ldc + n] = __halves2bfloat162(h0, h1);
                    *(__nv_bfloat162*)&outL[(size_t)m * ldc + n] = __halves2bfloat162(
                        __float2bfloat16(x0 - __bfloat162float(h0)),
                        __float2bfloat16(x1 - __bfloat162float(h1)));
                } else {
                    rsum += tanhf(x0 + dec[bofs + n] + cv) * v[n];
                    rsum += tanhf(x1 + dec[bofs + n + 1] + cv) * v[n + 1];
                }
            }
            if (mode == 2) {
                rsum += __shfl_xor_sync(0xffffffffu, rsum, 1);
                rsum += __shfl_xor_sync(0xffffffffu, rsum, 2);
                if (tig == 0) atomicAdd(&scores[m], rsum);
            }
        }
    }
}

// ============================ conversion kernels ============================
// fp32 -> bf16 hi/lo
__global__ void __launch_bounds__(256) csplit_bf(
    const float4* __restrict__ in, __nv_bfloat162* __restrict__ oh,
    __nv_bfloat162* __restrict__ ol, int n4)
{
    int i = blockIdx.x * 256 + threadIdx.x;
    if (i >= n4) return;
    float4 x = in[i];
    __nv_bfloat16 h0 = __float2bfloat16(x.x), h1 = __float2bfloat16(x.y);
    __nv_bfloat16 h2 = __float2bfloat16(x.z), h3 = __float2bfloat16(x.w);
    oh[2 * i]     = __halves2bfloat162(h0, h1);
    oh[2 * i + 1] = __halves2bfloat162(h2, h3);
    ol[2 * i]     = __halves2bfloat162(__float2bfloat16(x.x - __bfloat162float(h0)),
                                       __float2bfloat16(x.y - __bfloat162float(h1)));
    ol[2 * i + 1] = __halves2bfloat162(__float2bfloat16(x.z - __bfloat162float(h2)),
                                       __float2bfloat16(x.w - __bfloat162float(h3)));
}

// fp32 -> fp16 hi/lo
__global__ void __launch_bounds__(256) csplit_h(
    const float4* __restrict__ in, __half2* __restrict__ oh,
    __half2* __restrict__ ol, int n4)
{
    int i = blockIdx.x * 256 + threadIdx.x;
    if (i >= n4) return;
    float4 x = in[i];
    __half h0 = __float2half_rn(x.x), h1 = __float2half_rn(x.y);
    __half h2 = __float2half_rn(x.z), h3 = __float2half_rn(x.w);
    oh[2 * i]     = __halves2half2(h0, h1);
    oh[2 * i + 1] = __halves2half2(h2, h3);
    ol[2 * i]     = __halves2half2(__float2half_rn(x.x - __half2float(h0)),
                                   __float2half_rn(x.y - __half2float(h1)));
    ol[2 * i + 1] = __halves2half2(__float2half_rn(x.z - __half2float(h2)),
                                   __float2half_rn(x.w - __half2float(h3)));
}

// out[C,R] = bf16-split(in[R,C]^T)
__global__ void __launch_bounds__(256) tconv(
    const float* __restrict__ in, __nv_bfloat16* __restrict__ oh,
    __nv_bfloat16* __restrict__ ol, int R, int C)
{
    __shared__ float t[32][33];
    const int bx = blockIdx.x * 32, by = blockIdx.y * 32;
    const int x = threadIdx.x & 31, y = threadIdx.x >> 5;
#pragma unroll
    for (int i = 0; i < 32; i += 8)
        t[y + i][x] = in[(size_t)(by + y + i) * C + bx + x];
    __syncthreads();
#pragma unroll
    for (int i = 0; i < 32; i += 8) {
        float val = t[x][y + i];
        __nv_bfloat16 h = __float2bfloat16(val);
        size_t o = (size_t)(bx + y + i) * R + by + x;
        oh[o] = h;
        ol[o] = __float2bfloat16(val - __bfloat162float(h));
    }
}

// ============================ small kernels ============================
// b2 += partial(bg @ Gs) over K-chunk; chunk 0 adds bgs. b2 pre-zeroed.
__global__ void __launch_bounds__(256) b2_kernel(
    const float* __restrict__ bg, const float* __restrict__ Gs,
    const float* __restrict__ bgs, float* __restrict__ b2)
{
    const int j  = blockIdx.x * 256 + threadIdx.x;
    const int k0 = blockIdx.y * 512;
    float s = 0.f;
#pragma unroll 8
    for (int i = 0; i < 512; i++)
        s += bg[k0 + i] * Gs[(size_t)(k0 + i) * DH + j];
    if (blockIdx.y == 0) s += bgs[j];
    atomicAdd(&b2[j], s);
}

__global__ void __launch_bounds__(256) dec_kernel(
    const float* __restrict__ s_t_hat, const float* __restrict__ Wdec,
    const float* __restrict__ bdec, float* __restrict__ dec)
{
    const int idx = blockIdx.x * 256 + threadIdx.x;
    const int b = idx >> 10, j = idx & (DH - 1);
    float s = bdec[j];
#pragma unroll 8
    for (int k = 0; k < DH; k++) s += s_t_hat[b * DH + k] * Wdec[(size_t)k * DH + j];
    dec[idx] = s;
}

__global__ void __launch_bounds__(256) softmax_kernel(
    const float* __restrict__ scores, const float* __restrict__ cov,
    float* __restrict__ alpha, float* __restrict__ out)
{
    const int b = blockIdx.x, t = threadIdx.x;
    __shared__ float red[8];
    __shared__ float smax, ssum;
    float sv = (t < TK) ? scores[b * TK + t] : -3.4e38f;

    float m = sv;
#pragma unroll
    for (int o = 16; o > 0; o >>= 1) m = fmaxf(m, __shfl_xor_sync(0xffffffffu, m, o));
    if ((t & 31) == 0) red[t >> 5] = m;
    __syncthreads();
    if (t < 8) {
        m = red[t];
#pragma unroll
        for (int o = 4; o > 0; o >>= 1) m = fmaxf(m, __shfl_xor_sync(0xffu, m, o));
        if (t == 0) smax = m;
    }
    __syncthreads();

    float e = (t < TK) ? expf(sv - smax) : 0.f;
    float su = e;
#pragma unroll
    for (int o = 16; o > 0; o >>= 1) su += __shfl_xor_sync(0xffffffffu, su, o);
    if ((t & 31) == 0) red[t >> 5] = su;
    __syncthreads();
    if (t < 8) {
        su = red[t];
#pragma unroll
        for (int o = 4; o > 0; o >>= 1) su += __shfl_xor_sync(0xffu, su, o);
        if (t == 0) ssum = su;
    }
    __syncthreads();

    if (t < TK) {
        const float a = e / ssum;
        alpha[b * TK + t] = a;
        out[OUT_ALPHA + b * TK + t] = a;
        out[OUT_COV + b * TK + t] = cov[b * TK + t] + a;
    }
}

__global__ void __launch_bounds__(256) cimg_kernel(
    const float* __restrict__ gstar, const float* __restrict__ alpha,
    float* __restrict__ out)
{
    const int b = blockIdx.y;
    const int d = blockIdx.x * 256 + threadIdx.x;
    __shared__ float sal[TK];
    if (threadIdx.x < TK) sal[threadIdx.x] = alpha[b * TK + threadIdx.x];
    __syncthreads();
    float s = 0.f;
#pragma unroll 4
    for (int t = 0; t < TK; t++)
        s += sal[t] * gstar[((size_t)(b * TK + t)) * DH + d];
    out[OUT_C + b * DH + d] = s;
}

// ============================ launch ============================
extern "C" void kernel_launch(void* const* d_in, const int* in_sizes, int n_in,
                              void* d_out, int out_size)
{
    const float* gf   = (const float*)d_in[0];
    const float* sth  = (const float*)d_in[1];
    const float* cov  = (const float*)d_in[2];
    const float* Wg   = (const float*)d_in[3];
    const float* bg   = (const float*)d_in[4];
    const float* Gs   = (const float*)d_in[5];
    const float* bgs  = (const float*)d_in[6];
    const float* Wgs  = (const float*)d_in[7];
    const float* Wdec = (const float*)d_in[8];
    const float* bdec = (const float*)d_in[9];
    const float* v    = (const float*)d_in[10];
    float* out = (float*)d_out;

    __nv_bfloat16 *WgH, *WgL, *GsTH, *GsTL, *WgsTH, *WgsTL, *gsH, *gsL;
    __half *W2TF, *gfH, *gfL;
    float *gstarp, *b2p, *decp, *scoresp, *alphap;
    cudaGetSymbolAddress((void**)&WgH, g_WgH);     cudaGetSymbolAddress((void**)&WgL, g_WgL);
    cudaGetSymbolAddress((void**)&GsTH, g_GsTH);   cudaGetSymbolAddress((void**)&GsTL, g_GsTL);
    cudaGetSymbolAddress((void**)&W2TF, g_W2TF);
    cudaGetSymbolAddress((void**)&gfH, g_gfH);     cudaGetSymbolAddress((void**)&gfL, g_gfL);
    cudaGetSymbolAddress((void**)&WgsTH, g_WgsTH); cudaGetSymbolAddress((void**)&WgsTL, g_WgsTL);
    cudaGetSymbolAddress((void**)&gstarp, g_gstar);
    cudaGetSymbolAddress((void**)&gsH, g_gsH);     cudaGetSymbolAddress((void**)&gsL, g_gsL);
    cudaGetSymbolAddress((void**)&b2p, g_b2);      cudaGetSymbolAddress((void**)&decp, g_dec);
    cudaGetSymbolAddress((void**)&scoresp, g_scores);
    cudaGetSymbolAddress((void**)&alphap, g_alpha);

    cudaFuncSetAttribute(gemm_mma<3>, cudaFuncAttributeMaxDynamicSharedMemorySize, GEMM_SMEM);
    cudaFuncSetAttribute(gemm_mma<2>, cudaFuncAttributeMaxDynamicSharedMemorySize, GEMM_SMEM);

    // ---- single stream; launch indices chosen so slot 5 (ncu capture) = GEMM1 ----
    // (0) zero b2
    cudaMemsetAsync(b2p, 0, DH * sizeof(float));
    // (1) split Wg -> bf16 hi/lo
    csplit_bf<<<(GFD * GFD / 4 + 255) / 256, 256>>>((const float4*)Wg,
        (__nv_bfloat162*)WgH, (__nv_bfloat162*)WgL, GFD * GFD / 4);
    // (2) transpose+split Gs -> bf16 hi/lo
    {   dim3 g(DH / 32, GFD / 32);  tconv<<<g, 256>>>(Gs, GsTH, GsTL, GFD, DH); }
    // (3) b2 = bg @ Gs + bgs
    {   dim3 g(DH / 256, 8);  b2_kernel<<<g, 256>>>(bg, Gs, bgs, b2p); }
    // (4) zero scores
    cudaMemsetAsync(scoresp, 0, BT * sizeof(float));
    // (5) GEMM1 (bf16 3-pass): W2T[DH,GFD] = GsT @ Wg^T -> fp16 single, ldc=GFD
    {
        dim3 grid(GFD / 64, DH / 128);
        gemm_mma<3><<<grid, 128, GEMM_SMEM>>>(GsTH, GsTL, WgH, WgL, GFD, GFD / KTILE, 3, GFD,
            nullptr, nullptr, nullptr, nullptr, W2TF, nullptr, nullptr, nullptr, nullptr);
    }
    // (6) split gf -> fp16 hi/lo
    csplit_h<<<(BT * GFD / 4 + 255) / 256, 256>>>((const float4*)gf,
        (__half2*)gfH, (__half2*)gfL, BT * GFD / 4);
    // (7) transpose+split Wgs -> bf16 hi/lo
    {   dim3 g(DH / 32, DH / 32);  tconv<<<g, 256>>>(Wgs, WgsTH, WgsTL, DH, DH); }
    // (8) dec = s_t_hat @ Wdec + bdec
    dec_kernel<<<(BATCH * DH) / 256, 256>>>(sth, Wdec, bdec, decp);
    // (9) GEMM2 (fp16 2-pass): g_star = gf @ W2 + b2  [6272,1024], ldc=DH
    {
        dim3 grid(DH / 64, BT / 128);
        gemm_mma<2><<<grid, 128, GEMM_SMEM>>>(gfH, gfL, W2TF, nullptr, GFD, GFD / KTILE, 1, DH,
            gstarp, b2p, gsH, gsL, nullptr, nullptr, nullptr, nullptr, scoresp);
    }
    // (10) GEMM3 (bf16 3-pass, fused): scores = tanh(g_star@Wgs + dec + cov) . v
    {
        dim3 grid(DH / 64, BT / 128);
        gemm_mma<3><<<grid, 128, GEMM_SMEM>>>(gsH, gsL, WgsTH, WgsTL, DH, DH / KTILE, 2, DH,
            nullptr, nullptr, nullptr, nullptr, nullptr, decp, cov, v, scoresp);
    }
    // (11) softmax + outputs
    softmax_kernel<<<BATCH, 256>>>(scoresp, cov, alphap, out);
    // (12) context vector
    {   dim3 grid(DH / 256, BATCH);  cimg_kernel<<<grid, 256>>>(gstarp, alphap, out); }
}

// round 9
// speedup vs baseline: 1.7444x; 1.1400x over previous
#include <cuda_runtime.h>
#include <cuda_bf16.h>
#include <cuda_fp16.h>
#include <cstdint>
#include <math.h>

#define GFD   4096
#define DH    1024
#define BATCH 32
#define TK    196
#define BT    (BATCH * TK)   // 6272

// Output layout in d_out (float): c_img[32,1024] | coverage_new[32,196,1] | alpha[32,196,1]
#define OUT_C      0
#define OUT_COV    (BATCH * DH)
#define OUT_ALPHA  (BATCH * DH + BT)

// ============================ scratch (__device__ globals) ============================
__device__ __align__(1024) __half g_WgF[GFD * GFD];    // Wg fp16 single [GFD, GFD] (row-major, K contiguous)
__device__ __align__(1024) __half g_GsTH[DH * GFD];    // Gs^T fp16 hi [DH, GFD]
__device__ __align__(1024) __half g_GsTL[DH * GFD];    // Gs^T fp16 lo
__device__ __align__(1024) __half g_W2TF[DH * GFD];    // W2^T fp16 single [DH, GFD]
__device__ __align__(1024) __half g_gfH[BT * GFD];     // gf fp16 hi
__device__ __align__(1024) __half g_gfL[BT * GFD];     // gf fp16 lo
__device__ __align__(1024) __half g_WgsTF[DH * DH];    // Wgs^T fp16 single [DH, DH]
__device__ __align__(1024) float  g_gstar[BT * DH];
__device__ __align__(1024) __half g_gsH[BT * DH];      // g_star fp16 hi
__device__ __align__(1024) __half g_gsL[BT * DH];      // g_star fp16 lo
__device__ float g_b2[DH];
__device__ float g_dec[BATCH * DH];
__device__ float g_scores[BT];
__device__ float g_alpha[BT];

// ============================ helpers ============================
__device__ __forceinline__ uint32_t smem_u32(const void* p) {
    uint32_t a;
    asm("{ .reg .u64 t; cvta.to.shared.u64 t, %1; cvt.u32.u64 %0, t; }" : "=r"(a) : "l"(p));
    return a;
}
__device__ __forceinline__ void ldsm4(uint32_t* r, uint32_t addr) {
    asm volatile("ldmatrix.sync.aligned.m8n8.x4.shared.b16 {%0,%1,%2,%3}, [%4];"
                 : "=r"(r[0]), "=r"(r[1]), "=r"(r[2]), "=r"(r[3]) : "r"(addr));
}
__device__ __forceinline__ void mma_h(float* c, const uint32_t* a, const uint32_t* b) {
    asm volatile("mma.sync.aligned.m16n8k16.row.col.f32.f16.f16.f32 "
                 "{%0,%1,%2,%3}, {%4,%5,%6,%7}, {%8,%9}, {%0,%1,%2,%3};"
                 : "+f"(c[0]), "+f"(c[1]), "+f"(c[2]), "+f"(c[3])
                 : "r"(a[0]), "r"(a[1]), "r"(a[2]), "r"(a[3]), "r"(b[0]), "r"(b[1]));
}
__device__ __forceinline__ uint32_t swz(uint32_t off) {   // SW128: bits[6:4] ^= bits[9:7]
    return off ^ ((off >> 3) & 0x70);
}

// ============================ split-fp16 2-pass mma.sync GEMM ============================
// C[M,N] = Ah@Bh^T + Al@Bh^T  (A fp16 hi/lo, B single fp16), fp32 accum.
// A:[M,K] row-major, B:[N,K] row-major.
// CTA 128 threads (2x2 warps), tile 128x64, K-tile 64, double-buffered cp.async, 2 CTAs/SM.
#define KTILE     64
#define A_TILE_B  16384
#define B_TILE_B  8192
#define STG_B     (2 * A_TILE_B + B_TILE_B)       // AH AL BH = 40 KB
#define SM_AH(s)  ((s) * STG_B)
#define SM_AL(s)  (SM_AH(s) + A_TILE_B)
#define SM_BH(s)  (SM_AH(s) + 2 * A_TILE_B)
#define GEMM_SMEM (2 * STG_B)                     // 80 KB

__device__ __forceinline__ void issue_stage(
    uint32_t sb, int s, int kt,
    const char* Ah, const char* Al, const char* Bh,
    int K, int bm, int bn, int tid)
{
    const int k0 = kt * KTILE;
#pragma unroll
    for (int i = 0; i < 8; i++) {        // A: 128 rows x 8 cols(16B)
        int idx = tid + i * 128;
        int r = idx >> 3, c = idx & 7;
        uint32_t so = swz((uint32_t)(r * 128 + c * 16));
        size_t go = ((size_t)(bm + r) * K + k0 + c * 8) * 2;
        asm volatile("cp.async.cg.shared.global [%0], [%1], 16;" :: "r"(sb + SM_AH(s) + so), "l"(Ah + go) : "memory");
        asm volatile("cp.async.cg.shared.global [%0], [%1], 16;" :: "r"(sb + SM_AL(s) + so), "l"(Al + go) : "memory");
    }
#pragma unroll
    for (int i = 0; i < 4; i++) {        // B: 64 rows x 8 cols(16B)
        int idx = tid + i * 128;
        int r = idx >> 3, c = idx & 7;
        uint32_t so = swz((uint32_t)(r * 128 + c * 16));
        size_t go = ((size_t)(bn + r) * K + k0 + c * 8) * 2;
        asm volatile("cp.async.cg.shared.global [%0], [%1], 16;" :: "r"(sb + SM_BH(s) + so), "l"(Bh + go) : "memory");
    }
    asm volatile("cp.async.commit_group;" ::: "memory");
}

// mode 3: outF16[m*ldc+n] = D (fp16 single)          (W2^T)
// mode 1: outF = D + bias; emit fp16 hi/lo           (g_star)
// mode 2: scores[m] += sum_n tanh(D + dec + cov)*v   (fused attention scores)
__global__ void __launch_bounds__(128, 2) gemm_mma(
    const void* Ah_, const void* Al_, const void* Bh_,
    int K, int KT, int mode, int ldc,
    float* __restrict__ outF, const float* __restrict__ bias,
    __half* __restrict__ outH, __half* __restrict__ outL,
    __half* __restrict__ outF16,
    const float* __restrict__ dec, const float* __restrict__ cov,
    const float* __restrict__ v, float* __restrict__ scores)
{
    extern __shared__ char smem[];
    const uint32_t sb  = smem_u32(smem);
    const int tid  = threadIdx.x;
    const int wid  = tid >> 5, lane = tid & 31;
    const int wm   = wid & 1,  wn   = wid >> 1;     // warp grid 2(m) x 2(n)
    const int bm   = blockIdx.y * 128, bn = blockIdx.x * 64;
    const char* Ah = (const char*)Ah_;  const char* Al = (const char*)Al_;
    const char* Bh = (const char*)Bh_;

    float acc[4][4][4];
#pragma unroll
    for (int a = 0; a < 4; a++)
#pragma unroll
        for (int b = 0; b < 4; b++)
#pragma unroll
            for (int c = 0; c < 4; c++) acc[a][b][c] = 0.f;

    // per-lane ldmatrix offsets (within-tile)
    const uint32_t a_row  = (uint32_t)(wm * 64 + (lane & 15));                         // + mi*16
    const uint32_t a_kofs = (uint32_t)(((lane >> 4) & 1) * 16);                        // + kk*32
    const uint32_t b_row  = (uint32_t)(wn * 32 + (lane & 7) + ((lane >> 4) & 1) * 8);  // + nq*16
    const uint32_t b_kofs = (uint32_t)(((lane >> 3) & 1) * 16);                        // + kk*32

    issue_stage(sb, 0, 0, Ah, Al, Bh, K, bm, bn, tid);

    for (int kt = 0; kt < KT; kt++) {
        const int s = kt & 1;
        if (kt + 1 < KT) {
            issue_stage(sb, s ^ 1, kt + 1, Ah, Al, Bh, K, bm, bn, tid);
            asm volatile("cp.async.wait_group 1;" ::: "memory");
        } else {
            asm volatile("cp.async.wait_group 0;" ::: "memory");
        }
        __syncthreads();

        const uint32_t aH = sb + SM_AH(s), aL = sb + SM_AL(s);
        const uint32_t bH = sb + SM_BH(s);
#pragma unroll
        for (int kk = 0; kk < 4; kk++) {
            uint32_t fAh[4][4], fAl[4][4], fBh[2][4];
            // ---- pass 1: Ah x Bh (16 independent accumulators) ----
#pragma unroll
            for (int mi = 0; mi < 4; mi++) {
                uint32_t off = swz((a_row + mi * 16) * 128 + kk * 32 + a_kofs);
                ldsm4(fAh[mi], aH + off);
            }
#pragma unroll
            for (int nq = 0; nq < 2; nq++) {
                uint32_t off = swz((b_row + nq * 16) * 128 + kk * 32 + b_kofs);
                ldsm4(fBh[nq], bH + off);
            }
#pragma unroll
            for (int mi = 0; mi < 4; mi++)
#pragma unroll
                for (int nt = 0; nt < 4; nt++)
                    mma_h(acc[mi][nt], fAh[mi], &fBh[nt >> 1][(nt & 1) * 2]);

            // ---- pass 2: Al x Bh ----
#pragma unroll
            for (int mi = 0; mi < 4; mi++) {
                uint32_t off = swz((a_row + mi * 16) * 128 + kk * 32 + a_kofs);
                ldsm4(fAl[mi], aL + off);
            }
#pragma unroll
            for (int mi = 0; mi < 4; mi++)
#pragma unroll
                for (int nt = 0; nt < 4; nt++)
                    mma_h(acc[mi][nt], fAl[mi], &fBh[nt >> 1][(nt & 1) * 2]);
        }
        __syncthreads();
    }

    // ---------------- epilogue ----------------
    const int g = lane >> 2, tig = lane & 3;
#pragma unroll
    for (int mi = 0; mi < 4; mi++) {
#pragma unroll
        for (int h = 0; h < 2; h++) {
            const int m = bm + wm * 64 + mi * 16 + g + h * 8;
            float rsum = 0.f, cv = 0.f;
            int bofs = 0;
            if (mode == 2) { cv = cov[m]; bofs = (m / TK) * DH; }
#pragma unroll
            for (int nt = 0; nt < 4; nt++) {
                const int n = bn + wn * 32 + nt * 8 + 2 * tig;
                float x0 = acc[mi][nt][h * 2 + 0];
                float x1 = acc[mi][nt][h * 2 + 1];
                if (mode == 3) {
                    *(__half2*)&outF16[(size_t)m * ldc + n] = __floats2half2_rn(x0, x1);
                } else if (mode == 1) {
                    x0 += bias[n];  x1 += bias[n + 1];
                    *(float2*)&outF[(size_t)m * ldc + n] = make_float2(x0, x1);
                    __half h0 = __float2half_rn(x0), h1 = __float2half_rn(x1);
                    *(__half2*)&outH[(size_t)m * ldc + n] = __halves2half2(h0, h1);
                    *(__half2*)&outL[(size_t)m * ldc + n] = __halves2half2(
                        __float2half_rn(x0 - __half2float(h0)),
                        __float2half_rn(x1 - __half2float(h1)));
                } else {
                    rsum += tanhf(x0 + dec[bofs + n] + cv) * v[n];
                    rsum += tanhf(x1 + dec[bofs + n + 1] + cv) * v[n + 1];
                }
            }
            if (mode == 2) {
                rsum += __shfl_xor_sync(0xffffffffu, rsum, 1);
                rsum += __shfl_xor_sync(0xffffffffu, rsum, 2);
                if (tig == 0) atomicAdd(&scores[m], rsum);
            }
        }
    }
}

// ============================ conversion kernels ============================
// fp32 -> fp16 hi/lo
__global__ void __launch_bounds__(256) csplit_h(
    const float4* __restrict__ in, __half2* __restrict__ oh,
    __half2* __restrict__ ol, int n4)
{
    int i = blockIdx.x * 256 + threadIdx.x;
    if (i >= n4) return;
    float4 x = in[i];
    __half h0 = __float2half_rn(x.x), h1 = __float2half_rn(x.y);
    __half h2 = __float2half_rn(x.z), h3 = __float2half_rn(x.w);
    oh[2 * i]     = __halves2half2(h0, h1);
    oh[2 * i + 1] = __halves2half2(h2, h3);
    ol[2 * i]     = __halves2half2(__float2half_rn(x.x - __half2float(h0)),
                                   __float2half_rn(x.y - __half2float(h1)));
    ol[2 * i + 1] = __halves2half2(__float2half_rn(x.z - __half2float(h2)),
                                   __float2half_rn(x.w - __half2float(h3)));
}

// fp32 -> fp16 single
__global__ void __launch_bounds__(256) csingle_h(
    const float4* __restrict__ in, __half2* __restrict__ oh, int n4)
{
    int i = blockIdx.x * 256 + threadIdx.x;
    if (i >= n4) return;
    float4 x = in[i];
    oh[2 * i]     = __floats2half2_rn(x.x, x.y);
    oh[2 * i + 1] = __floats2half2_rn(x.z, x.w);
}

// out[C,R] = fp16-hi/lo split of in[R,C]^T
__global__ void __launch_bounds__(256) tconv_h2(
    const float* __restrict__ in, __half* __restrict__ oh,
    __half* __restrict__ ol, int R, int C)
{
    __shared__ float t[32][33];
    const int bx = blockIdx.x * 32, by = blockIdx.y * 32;
    const int x = threadIdx.x & 31, y = threadIdx.x >> 5;
#pragma unroll
    for (int i = 0; i < 32; i += 8)
        t[y + i][x] = in[(size_t)(by + y + i) * C + bx + x];
    __syncthreads();
#pragma unroll
    for (int i = 0; i < 32; i += 8) {
        float val = t[x][y + i];
        __half h = __float2half_rn(val);
        size_t o = (size_t)(bx + y + i) * R + by + x;
        oh[o] = h;
        ol[o] = __float2half_rn(val - __half2float(h));
    }
}

// out[C,R] = fp16 single of in[R,C]^T
__global__ void __launch_bounds__(256) tconv_h1(
    const float* __restrict__ in, __half* __restrict__ oh, int R, int C)
{
    __shared__ float t[32][33];
    const int bx = blockIdx.x * 32, by = blockIdx.y * 32;
    const int x = threadIdx.x & 31, y = threadIdx.x >> 5;
#pragma unroll
    for (int i = 0; i < 32; i += 8)
        t[y + i][x] = in[(size_t)(by + y + i) * C + bx + x];
    __syncthreads();
#pragma unroll
    for (int i = 0; i < 32; i += 8) {
        float val = t[x][y + i];
        oh[(size_t)(bx + y + i) * R + by + x] = __float2half_rn(val);
    }
}

// ============================ small kernels ============================
// b2 += partial(bg @ Gs) over K-chunk; chunk 0 adds bgs. b2 pre-zeroed.
__global__ void __launch_bounds__(256) b2_kernel(
    const float* __restrict__ bg, const float* __restrict__ Gs,
    const float* __restrict__ bgs, float* __restrict__ b2)
{
    const int j  = blockIdx.x * 256 + threadIdx.x;
    const int k0 = blockIdx.y * 512;
    float s = 0.f;
#pragma unroll 8
    for (int i = 0; i < 512; i++)
        s += bg[k0 + i] * Gs[(size_t)(k0 + i) * DH + j];
    if (blockIdx.y == 0) s += bgs[j];
    atomicAdd(&b2[j], s);
}

__global__ void __launch_bounds__(256) dec_kernel(
    const float* __restrict__ s_t_hat, const float* __restrict__ Wdec,
    const float* __restrict__ bdec, float* __restrict__ dec)
{
    const int idx = blockIdx.x * 256 + threadIdx.x;
    const int b = idx >> 10, j = idx & (DH - 1);
    float s = bdec[j];
#pragma unroll 8
    for (int k = 0; k < DH; k++) s += s_t_hat[b * DH + k] * Wdec[(size_t)k * DH + j];
    dec[idx] = s;
}

__global__ void __launch_bounds__(256) softmax_kernel(
    const float* __restrict__ scores, const float* __restrict__ cov,
    float* __restrict__ alpha, float* __restrict__ out)
{
    const int b = blockIdx.x, t = threadIdx.x;
    __shared__ float red[8];
    __shared__ float smax, ssum;
    float sv = (t < TK) ? scores[b * TK + t] : -3.4e38f;

    float m = sv;
#pragma unroll
    for (int o = 16; o > 0; o >>= 1) m = fmaxf(m, __shfl_xor_sync(0xffffffffu, m, o));
    if ((t & 31) == 0) red[t >> 5] = m;
    __syncthreads();
    if (t < 8) {
        m = red[t];
#pragma unroll
        for (int o = 4; o > 0; o >>= 1) m = fmaxf(m, __shfl_xor_sync(0xffu, m, o));
        if (t == 0) smax = m;
    }
    __syncthreads();

    float e = (t < TK) ? expf(sv - smax) : 0.f;
    float su = e;
#pragma unroll
    for (int o = 16; o > 0; o >>= 1) su += __shfl_xor_sync(0xffffffffu, su, o);
    if ((t & 31) == 0) red[t >> 5] = su;
    __syncthreads();
    if (t < 8) {
        su = red[t];
#pragma unroll
        for (int o = 4; o > 0; o >>= 1) su += __shfl_xor_sync(0xffu, su, o);
        if (t == 0) ssum = su;
    }
    __syncthreads();

    if (t < TK) {
        const float a = e / ssum;
        alpha[b * TK + t] = a;
        out[OUT_ALPHA + b * TK + t] = a;
        out[OUT_COV + b * TK + t] = cov[b * TK + t] + a;
    }
}

__global__ void __launch_bounds__(256) cimg_kernel(
    const float* __restrict__ gstar, const float* __restrict__ alpha,
    float* __restrict__ out)
{
    const int b = blockIdx.y;
    const int d = blockIdx.x * 256 + threadIdx.x;
    __shared__ float sal[TK];
    if (threadIdx.x < TK) sal[threadIdx.x] = alpha[b * TK + threadIdx.x];
    __syncthreads();
    float s = 0.f;
#pragma unroll 4
    for (int t = 0; t < TK; t++)
        s += sal[t] * gstar[((size_t)(b * TK + t)) * DH + d];
    out[OUT_C + b * DH + d] = s;
}

// ============================ launch ============================
extern "C" void kernel_launch(void* const* d_in, const int* in_sizes, int n_in,
                              void* d_out, int out_size)
{
    const float* gf   = (const float*)d_in[0];
    const float* sth  = (const float*)d_in[1];
    const float* cov  = (const float*)d_in[2];
    const float* Wg   = (const float*)d_in[3];
    const float* bg   = (const float*)d_in[4];
    const float* Gs   = (const float*)d_in[5];
    const float* bgs  = (const float*)d_in[6];
    const float* Wgs  = (const float*)d_in[7];
    const float* Wdec = (const float*)d_in[8];
    const float* bdec = (const float*)d_in[9];
    const float* v    = (const float*)d_in[10];
    float* out = (float*)d_out;

    __half *WgF, *GsTH, *GsTL, *W2TF, *gfH, *gfL, *WgsTF, *gsH, *gsL;
    float *gstarp, *b2p, *decp, *scoresp, *alphap;
    cudaGetSymbolAddress((void**)&WgF, g_WgF);
    cudaGetSymbolAddress((void**)&GsTH, g_GsTH);   cudaGetSymbolAddress((void**)&GsTL, g_GsTL);
    cudaGetSymbolAddress((void**)&W2TF, g_W2TF);
    cudaGetSymbolAddress((void**)&gfH, g_gfH);     cudaGetSymbolAddress((void**)&gfL, g_gfL);
    cudaGetSymbolAddress((void**)&WgsTF, g_WgsTF);
    cudaGetSymbolAddress((void**)&gstarp, g_gstar);
    cudaGetSymbolAddress((void**)&gsH, g_gsH);     cudaGetSymbolAddress((void**)&gsL, g_gsL);
    cudaGetSymbolAddress((void**)&b2p, g_b2);      cudaGetSymbolAddress((void**)&decp, g_dec);
    cudaGetSymbolAddress((void**)&scoresp, g_scores);
    cudaGetSymbolAddress((void**)&alphap, g_alpha);

    cudaFuncSetAttribute(gemm_mma, cudaFuncAttributeMaxDynamicSharedMemorySize, GEMM_SMEM);

    // ---- single stream; slot 5 (ncu capture) = GEMM1 ----
    // (0) zero b2
    cudaMemsetAsync(b2p, 0, DH * sizeof(float));
    // (1) Wg -> fp16 single (row-major; serves directly as GEMM1's B)
    csingle_h<<<(GFD * GFD / 4 + 255) / 256, 256>>>((const float4*)Wg, (__half2*)WgF, GFD * GFD / 4);
    // (2) Gs -> Gs^T fp16 hi/lo
    {   dim3 g(DH / 32, GFD / 32);  tconv_h2<<<g, 256>>>(Gs, GsTH, GsTL, GFD, DH); }
    // (3) b2 = bg @ Gs + bgs
    {   dim3 g(DH / 256, 8);  b2_kernel<<<g, 256>>>(bg, Gs, bgs, b2p); }
    // (4) zero scores
    cudaMemsetAsync(scoresp, 0, BT * sizeof(float));
    // (5) GEMM1: W2T[DH,GFD] = GsT @ Wg^T -> fp16 single, ldc=GFD
    //     C[d,g] = sum_k GsT[d,k] * Wg[g,k]  (A=GsT hi/lo, B=Wg single)
    {
        dim3 grid(GFD / 64, DH / 128);
        gemm_mma<<<grid, 128, GEMM_SMEM>>>(GsTH, GsTL, WgF, GFD, GFD / KTILE, 3, GFD,
            nullptr, nullptr, nullptr, nullptr, W2TF, nullptr, nullptr, nullptr, nullptr);
    }
    // (6) gf -> fp16 hi/lo
    csplit_h<<<(BT * GFD / 4 + 255) / 256, 256>>>((const float4*)gf,
        (__half2*)gfH, (__half2*)gfL, BT * GFD / 4);
    // (7) Wgs -> Wgs^T fp16 single
    {   dim3 g(DH / 32, DH / 32);  tconv_h1<<<g, 256>>>(Wgs, WgsTF, DH, DH); }
    // (8) dec = s_t_hat @ Wdec + bdec
    dec_kernel<<<(BATCH * DH) / 256, 256>>>(sth, Wdec, bdec, decp);
    // (9) GEMM2: g_star = gf @ W2 + b2  [6272,1024] (A=gf hi/lo, B=W2T single), ldc=DH
    {
        dim3 grid(DH / 64, BT / 128);
        gemm_mma<<<grid, 128, GEMM_SMEM>>>(gfH, gfL, W2TF, GFD, GFD / KTILE, 1, DH,
            gstarp, b2p, gsH, gsL, nullptr, nullptr, nullptr, nullptr, scoresp);
    }
    // (10) GEMM3 (fused): scores = tanh(g_star@Wgs + dec + cov) . v  (A=g_star hi/lo, B=WgsT single)
    {
        dim3 grid(DH / 64, BT / 128);
        gemm_mma<<<grid, 128, GEMM_SMEM>>>(gsH, gsL, WgsTF, DH, DH / KTILE, 2, DH,
            nullptr, nullptr, nullptr, nullptr, nullptr, decp, cov, v, scoresp);
    }
    // (11) softmax + outputs
    softmax_kernel<<<BATCH, 256>>>(scoresp, cov, alphap, out);
    // (12) context vector
    {   dim3 grid(DH / 256, BATCH);  cimg_kernel<<<grid, 256>>>(gstarp, alphap, out); }
}

// round 10
// speedup vs baseline: 2.4086x; 1.3808x over previous
#include <cuda_runtime.h>
#include <cuda_bf16.h>
#include <cuda_fp16.h>
#include <cstdint>
#include <math.h>

#define GFD   4096
#define DH    1024
#define BATCH 32
#define TK    196
#define BT    (BATCH * TK)   // 6272

// Output layout in d_out (float): c_img[32,1024] | coverage_new[32,196,1] | alpha[32,196,1]
#define OUT_C      0
#define OUT_COV    (BATCH * DH)
#define OUT_ALPHA  (BATCH * DH + BT)

// ============================ scratch (__device__ globals) ============================
__device__ __align__(1024) __half g_WgF[GFD * GFD];    // Wg fp16 [GFD, GFD] row-major (K contiguous)
__device__ __align__(1024) __half g_GsTF[DH * GFD];    // Gs^T fp16 single [DH, GFD]
__device__ __align__(1024) __half g_W2TF[DH * GFD];    // W2^T fp16 single [DH, GFD]
__device__ __align__(1024) __half g_gfF[BT * GFD];     // gf fp16 single
__device__ __align__(1024) __half g_WgsTF[DH * DH];    // Wgs^T fp16 single [DH, DH]
__device__ __align__(1024) float  g_gstar[BT * DH];
__device__ __align__(1024) __half g_gsH[BT * DH];      // g_star fp16 hi
__device__ __align__(1024) __half g_gsL[BT * DH];      // g_star fp16 lo
__device__ float g_b2[DH];
__device__ float g_dec[BATCH * DH];
__device__ float g_scores[BT];
__device__ float g_alpha[BT];

// ============================ helpers ============================
__device__ __forceinline__ uint32_t smem_u32(const void* p) {
    uint32_t a;
    asm("{ .reg .u64 t; cvta.to.shared.u64 t, %1; cvt.u32.u64 %0, t; }" : "=r"(a) : "l"(p));
    return a;
}
__device__ __forceinline__ void ldsm4(uint32_t* r, uint32_t addr) {
    asm volatile("ldmatrix.sync.aligned.m8n8.x4.shared.b16 {%0,%1,%2,%3}, [%4];"
                 : "=r"(r[0]), "=r"(r[1]), "=r"(r[2]), "=r"(r[3]) : "r"(addr));
}
__device__ __forceinline__ void mma_h(float* c, const uint32_t* a, const uint32_t* b) {
    asm volatile("mma.sync.aligned.m16n8k16.row.col.f32.f16.f16.f32 "
                 "{%0,%1,%2,%3}, {%4,%5,%6,%7}, {%8,%9}, {%0,%1,%2,%3};"
                 : "+f"(c[0]), "+f"(c[1]), "+f"(c[2]), "+f"(c[3])
                 : "r"(a[0]), "r"(a[1]), "r"(a[2]), "r"(a[3]), "r"(b[0]), "r"(b[1]));
}
__device__ __forceinline__ uint32_t swz(uint32_t off) {   // SW128: bits[6:4] ^= bits[9:7]
    return off ^ ((off >> 3) & 0x70);
}

// ============================ fp16 mma.sync GEMM (1- or 2-pass A) ============================
// NPASS=1: C = A@B^T           (A single fp16)
// NPASS=2: C = Ah@B^T + Al@B^T (A fp16 hi/lo)
// A:[M,K] row-major, B:[N,K] row-major, fp32 accum.
// CTA 128 threads (2x2 warps), tile 128x64, K-tile 64, double-buffered cp.async, 2 CTAs/SM.
#define KTILE     64
#define A_TILE_B  16384
#define B_TILE_B  8192
#define STG_B     (2 * A_TILE_B + B_TILE_B)       // AH AL BH = 40 KB (AL unused when NPASS=1)
#define SM_AH(s)  ((s) * STG_B)
#define SM_AL(s)  (SM_AH(s) + A_TILE_B)
#define SM_BH(s)  (SM_AH(s) + 2 * A_TILE_B)
#define GEMM_SMEM (2 * STG_B)                     // 80 KB

template<int NPASS>
__device__ __forceinline__ void issue_stage(
    uint32_t sb, int s, int kt,
    const char* Ah, const char* Al, const char* Bh,
    int K, int bm, int bn, int tid)
{
    const int k0 = kt * KTILE;
#pragma unroll
    for (int i = 0; i < 8; i++) {        // A: 128 rows x 8 cols(16B)
        int idx = tid + i * 128;
        int r = idx >> 3, c = idx & 7;
        uint32_t so = swz((uint32_t)(r * 128 + c * 16));
        size_t go = ((size_t)(bm + r) * K + k0 + c * 8) * 2;
        asm volatile("cp.async.cg.shared.global [%0], [%1], 16;" :: "r"(sb + SM_AH(s) + so), "l"(Ah + go) : "memory");
        if constexpr (NPASS == 2) {
            asm volatile("cp.async.cg.shared.global [%0], [%1], 16;" :: "r"(sb + SM_AL(s) + so), "l"(Al + go) : "memory");
        }
    }
#pragma unroll
    for (int i = 0; i < 4; i++) {        // B: 64 rows x 8 cols(16B)
        int idx = tid + i * 128;
        int r = idx >> 3, c = idx & 7;
        uint32_t so = swz((uint32_t)(r * 128 + c * 16));
        size_t go = ((size_t)(bn + r) * K + k0 + c * 8) * 2;
        asm volatile("cp.async.cg.shared.global [%0], [%1], 16;" :: "r"(sb + SM_BH(s) + so), "l"(Bh + go) : "memory");
    }
    asm volatile("cp.async.commit_group;" ::: "memory");
}

// mode 3: outF16[m*ldc+n] = D (fp16 single)          (W2^T)
// mode 1: outF = D + bias; emit fp16 hi/lo           (g_star)
// mode 2: scores[m] += sum_n tanh(D + dec + cov)*v   (fused attention scores)
template<int NPASS>
__global__ void __launch_bounds__(128, 2) gemm_mma(
    const void* Ah_, const void* Al_, const void* Bh_,
    int K, int KT, int mode, int ldc,
    float* __restrict__ outF, const float* __restrict__ bias,
    __half* __restrict__ outH, __half* __restrict__ outL,
    __half* __restrict__ outF16,
    const float* __restrict__ dec, const float* __restrict__ cov,
    const float* __restrict__ v, float* __restrict__ scores)
{
    extern __shared__ char smem[];
    const uint32_t sb  = smem_u32(smem);
    const int tid  = threadIdx.x;
    const int wid  = tid >> 5, lane = tid & 31;
    const int wm   = wid & 1,  wn   = wid >> 1;     // warp grid 2(m) x 2(n)
    const int bm   = blockIdx.y * 128, bn = blockIdx.x * 64;
    const char* Ah = (const char*)Ah_;  const char* Al = (const char*)Al_;
    const char* Bh = (const char*)Bh_;

    float acc[4][4][4];
#pragma unroll
    for (int a = 0; a < 4; a++)
#pragma unroll
        for (int b = 0; b < 4; b++)
#pragma unroll
            for (int c = 0; c < 4; c++) acc[a][b][c] = 0.f;

    // per-lane ldmatrix offsets (within-tile)
    const uint32_t a_row  = (uint32_t)(wm * 64 + (lane & 15));                         // + mi*16
    const uint32_t a_kofs = (uint32_t)(((lane >> 4) & 1) * 16);                        // + kk*32
    const uint32_t b_row  = (uint32_t)(wn * 32 + (lane & 7) + ((lane >> 4) & 1) * 8);  // + nq*16
    const uint32_t b_kofs = (uint32_t)(((lane >> 3) & 1) * 16);                        // + kk*32

    issue_stage<NPASS>(sb, 0, 0, Ah, Al, Bh, K, bm, bn, tid);

    for (int kt = 0; kt < KT; kt++) {
        const int s = kt & 1;
        if (kt + 1 < KT) {
            issue_stage<NPASS>(sb, s ^ 1, kt + 1, Ah, Al, Bh, K, bm, bn, tid);
            asm volatile("cp.async.wait_group 1;" ::: "memory");
        } else {
            asm volatile("cp.async.wait_group 0;" ::: "memory");
        }
        __syncthreads();

        const uint32_t aH = sb + SM_AH(s), aL = sb + SM_AL(s);
        const uint32_t bH = sb + SM_BH(s);
#pragma unroll
        for (int kk = 0; kk < 4; kk++) {
            uint32_t fAh[4][4], fBh[2][4];
            // ---- pass 1: Ah x Bh (16 independent accumulators) ----
#pragma unroll
            for (int mi = 0; mi < 4; mi++) {
                uint32_t off = swz((a_row + mi * 16) * 128 + kk * 32 + a_kofs);
                ldsm4(fAh[mi], aH + off);
            }
#pragma unroll
            for (int nq = 0; nq < 2; nq++) {
                uint32_t off = swz((b_row + nq * 16) * 128 + kk * 32 + b_kofs);
                ldsm4(fBh[nq], bH + off);
            }
#pragma unroll
            for (int mi = 0; mi < 4; mi++)
#pragma unroll
                for (int nt = 0; nt < 4; nt++)
                    mma_h(acc[mi][nt], fAh[mi], &fBh[nt >> 1][(nt & 1) * 2]);

            // ---- pass 2 (NPASS==2): Al x Bh ----
            if constexpr (NPASS == 2) {
                uint32_t fAl[4][4];
#pragma unroll
                for (int mi = 0; mi < 4; mi++) {
                    uint32_t off = swz((a_row + mi * 16) * 128 + kk * 32 + a_kofs);
                    ldsm4(fAl[mi], aL + off);
                }
#pragma unroll
                for (int mi = 0; mi < 4; mi++)
#pragma unroll
                    for (int nt = 0; nt < 4; nt++)
                        mma_h(acc[mi][nt], fAl[mi], &fBh[nt >> 1][(nt & 1) * 2]);
            }
        }
        __syncthreads();
    }

    // ---------------- epilogue ----------------
    const int g = lane >> 2, tig = lane & 3;
#pragma unroll
    for (int mi = 0; mi < 4; mi++) {
#pragma unroll
        for (int h = 0; h < 2; h++) {
            const int m = bm + wm * 64 + mi * 16 + g + h * 8;
            float rsum = 0.f, cv = 0.f;
            int bofs = 0;
            if (mode == 2) { cv = cov[m]; bofs = (m / TK) * DH; }
#pragma unroll
            for (int nt = 0; nt < 4; nt++) {
                const int n = bn + wn * 32 + nt * 8 + 2 * tig;
                float x0 = acc[mi][nt][h * 2 + 0];
                float x1 = acc[mi][nt][h * 2 + 1];
                if (mode == 3) {
                    *(__half2*)&outF16[(size_t)m * ldc + n] = __floats2half2_rn(x0, x1);
                } else if (mode == 1) {
                    x0 += bias[n];  x1 += bias[n + 1];
                    *(float2*)&outF[(size_t)m * ldc + n] = make_float2(x0, x1);
                    __half h0 = __float2half_rn(x0), h1 = __float2half_rn(x1);
                    *(__half2*)&outH[(size_t)m * ldc + n] = __halves2half2(h0, h1);
                    *(__half2*)&outL[(size_t)m * ldc + n] = __halves2half2(
                        __float2half_rn(x0 - __half2float(h0)),
                        __float2half_rn(x1 - __half2float(h1)));
                } else {
                    rsum += tanhf(x0 + dec[bofs + n] + cv) * v[n];
                    rsum += tanhf(x1 + dec[bofs + n + 1] + cv) * v[n + 1];
                }
            }
            if (mode == 2) {
                rsum += __shfl_xor_sync(0xffffffffu, rsum, 1);
                rsum += __shfl_xor_sync(0xffffffffu, rsum, 2);
                if (tig == 0) atomicAdd(&scores[m], rsum);
            }
        }
    }
}

// ============================ conversion kernels ============================
// fp32 -> fp16 single
__global__ void __launch_bounds__(256) csingle_h(
    const float4* __restrict__ in, __half2* __restrict__ oh, int n4)
{
    int i = blockIdx.x * 256 + threadIdx.x;
    if (i >= n4) return;
    float4 x = in[i];
    oh[2 * i]     = __floats2half2_rn(x.x, x.y);
    oh[2 * i + 1] = __floats2half2_rn(x.z, x.w);
}

// out[C,R] = fp16 single of in[R,C]^T
__global__ void __launch_bounds__(256) tconv_h1(
    const float* __restrict__ in, __half* __restrict__ oh, int R, int C)
{
    __shared__ float t[32][33];
    const int bx = blockIdx.x * 32, by = blockIdx.y * 32;
    const int x = threadIdx.x & 31, y = threadIdx.x >> 5;
#pragma unroll
    for (int i = 0; i < 32; i += 8)
        t[y + i][x] = in[(size_t)(by + y + i) * C + bx + x];
    __syncthreads();
#pragma unroll
    for (int i = 0; i < 32; i += 8) {
        float val = t[x][y + i];
        oh[(size_t)(bx + y + i) * R + by + x] = __float2half_rn(val);
    }
}

// ============================ small kernels ============================
// b2 += partial(bg @ Gs) over K-chunk; chunk 0 adds bgs. b2 pre-zeroed.
__global__ void __launch_bounds__(256) b2_kernel(
    const float* __restrict__ bg, const float* __restrict__ Gs,
    const float* __restrict__ bgs, float* __restrict__ b2)
{
    const int j  = blockIdx.x * 256 + threadIdx.x;
    const int k0 = blockIdx.y * 512;
    float s = 0.f;
#pragma unroll 8
    for (int i = 0; i < 512; i++)
        s += bg[k0 + i] * Gs[(size_t)(k0 + i) * DH + j];
    if (blockIdx.y == 0) s += bgs[j];
    atomicAdd(&b2[j], s);
}

__global__ void __launch_bounds__(256) dec_kernel(
    const float* __restrict__ s_t_hat, const float* __restrict__ Wdec,
    const float* __restrict__ bdec, float* __restrict__ dec)
{
    const int idx = blockIdx.x * 256 + threadIdx.x;
    const int b = idx >> 10, j = idx & (DH - 1);
    float s = bdec[j];
#pragma unroll 8
    for (int k = 0; k < DH; k++) s += s_t_hat[b * DH + k] * Wdec[(size_t)k * DH + j];
    dec[idx] = s;
}

__global__ void __launch_bounds__(256) softmax_kernel(
    const float* __restrict__ scores, const float* __restrict__ cov,
    float* __restrict__ alpha, float* __restrict__ out)
{
    const int b = blockIdx.x, t = threadIdx.x;
    __shared__ float red[8];
    __shared__ float smax, ssum;
    float sv = (t < TK) ? scores[b * TK + t] : -3.4e38f;

    float m = sv;
#pragma unroll
    for (int o = 16; o > 0; o >>= 1) m = fmaxf(m, __shfl_xor_sync(0xffffffffu, m, o));
    if ((t & 31) == 0) red[t >> 5] = m;
    __syncthreads();
    if (t < 8) {
        m = red[t];
#pragma unroll
        for (int o = 4; o > 0; o >>= 1) m = fmaxf(m, __shfl_xor_sync(0xffu, m, o));
        if (t == 0) smax = m;
    }
    __syncthreads();

    float e = (t < TK) ? expf(sv - smax) : 0.f;
    float su = e;
#pragma unroll
    for (int o = 16; o > 0; o >>= 1) su += __shfl_xor_sync(0xffffffffu, su, o);
    if ((t & 31) == 0) red[t >> 5] = su;
    __syncthreads();
    if (t < 8) {
        su = red[t];
#pragma unroll
        for (int o = 4; o > 0; o >>= 1) su += __shfl_xor_sync(0xffu, su, o);
        if (t == 0) ssum = su;
    }
    __syncthreads();

    if (t < TK) {
        const float a = e / ssum;
        alpha[b * TK + t] = a;
        out[OUT_ALPHA + b * TK + t] = a;
        out[OUT_COV + b * TK + t] = cov[b * TK + t] + a;
    }
}

__global__ void __launch_bounds__(256) cimg_kernel(
    const float* __restrict__ gstar, const float* __restrict__ alpha,
    float* __restrict__ out)
{
    const int b = blockIdx.y;
    const int d = blockIdx.x * 256 + threadIdx.x;
    __shared__ float sal[TK];
    if (threadIdx.x < TK) sal[threadIdx.x] = alpha[b * TK + threadIdx.x];
    __syncthreads();
    float s = 0.f;
#pragma unroll 4
    for (int t = 0; t < TK; t++)
        s += sal[t] * gstar[((size_t)(b * TK + t)) * DH + d];
    out[OUT_C + b * DH + d] = s;
}

// ============================ launch ============================
extern "C" void kernel_launch(void* const* d_in, const int* in_sizes, int n_in,
                              void* d_out, int out_size)
{
    const float* gf   = (const float*)d_in[0];
    const float* sth  = (const float*)d_in[1];
    const float* cov  = (const float*)d_in[2];
    const float* Wg   = (const float*)d_in[3];
    const float* bg   = (const float*)d_in[4];
    const float* Gs   = (const float*)d_in[5];
    const float* bgs  = (const float*)d_in[6];
    const float* Wgs  = (const float*)d_in[7];
    const float* Wdec = (const float*)d_in[8];
    const float* bdec = (const float*)d_in[9];
    const float* v    = (const float*)d_in[10];
    float* out = (float*)d_out;

    __half *WgF, *GsTF, *W2TF, *gfF, *WgsTF, *gsH, *gsL;
    float *gstarp, *b2p, *decp, *scoresp, *alphap;
    cudaGetSymbolAddress((void**)&WgF, g_WgF);
    cudaGetSymbolAddress((void**)&GsTF, g_GsTF);
    cudaGetSymbolAddress((void**)&W2TF, g_W2TF);
    cudaGetSymbolAddress((void**)&gfF, g_gfF);
    cudaGetSymbolAddress((void**)&WgsTF, g_WgsTF);
    cudaGetSymbolAddress((void**)&gstarp, g_gstar);
    cudaGetSymbolAddress((void**)&gsH, g_gsH);     cudaGetSymbolAddress((void**)&gsL, g_gsL);
    cudaGetSymbolAddress((void**)&b2p, g_b2);      cudaGetSymbolAddress((void**)&decp, g_dec);
    cudaGetSymbolAddress((void**)&scoresp, g_scores);
    cudaGetSymbolAddress((void**)&alphap, g_alpha);

    cudaFuncSetAttribute(gemm_mma<1>, cudaFuncAttributeMaxDynamicSharedMemorySize, GEMM_SMEM);
    cudaFuncSetAttribute(gemm_mma<2>, cudaFuncAttributeMaxDynamicSharedMemorySize, GEMM_SMEM);

    // ---- single stream; slot 5 (ncu capture) = GEMM1 ----
    // (0) zero b2
    cudaMemsetAsync(b2p, 0, DH * sizeof(float));
    // (1) Wg -> fp16 single (row-major; GEMM1's B)
    csingle_h<<<(GFD * GFD / 4 + 255) / 256, 256>>>((const float4*)Wg, (__half2*)WgF, GFD * GFD / 4);
    // (2) Gs -> Gs^T fp16 single
    {   dim3 g(DH / 32, GFD / 32);  tconv_h1<<<g, 256>>>(Gs, GsTF, GFD, DH); }
    // (3) b2 = bg @ Gs + bgs
    {   dim3 g(DH / 256, 8);  b2_kernel<<<g, 256>>>(bg, Gs, bgs, b2p); }
    // (4) zero scores
    cudaMemsetAsync(scoresp, 0, BT * sizeof(float));
    // (5) GEMM1 (1-pass): W2T[DH,GFD] = GsT @ Wg^T -> fp16 single, ldc=GFD
    {
        dim3 grid(GFD / 64, DH / 128);
        gemm_mma<1><<<grid, 128, GEMM_SMEM>>>(GsTF, nullptr, WgF, GFD, GFD / KTILE, 3, GFD,
            nullptr, nullptr, nullptr, nullptr, W2TF, nullptr, nullptr, nullptr, nullptr);
    }
    // (6) gf -> fp16 single
    csingle_h<<<(BT * GFD / 4 + 255) / 256, 256>>>((const float4*)gf, (__half2*)gfF, BT * GFD / 4);
    // (7) Wgs -> Wgs^T fp16 single
    {   dim3 g(DH / 32, DH / 32);  tconv_h1<<<g, 256>>>(Wgs, WgsTF, DH, DH); }
    // (8) dec = s_t_hat @ Wdec + bdec
    dec_kernel<<<(BATCH * DH) / 256, 256>>>(sth, Wdec, bdec, decp);
    // (9) GEMM2 (1-pass): g_star = gf @ W2 + b2  [6272,1024], ldc=DH; emits fp16 hi/lo
    {
        dim3 grid(DH / 64, BT / 128);
        gemm_mma<1><<<grid, 128, GEMM_SMEM>>>(gfF, nullptr, W2TF, GFD, GFD / KTILE, 1, DH,
            gstarp, b2p, gsH, gsL, nullptr, nullptr, nullptr, nullptr, scoresp);
    }
    // (10) GEMM3 (2-pass, fused): scores = tanh(g_star@Wgs + dec + cov) . v
    {
        dim3 grid(DH / 64, BT / 128);
        gemm_mma<2><<<grid, 128, GEMM_SMEM>>>(gsH, gsL, WgsTF, DH, DH / KTILE, 2, DH,
            nullptr, nullptr, nullptr, nullptr, nullptr, decp, cov, v, scoresp);
    }
    // (11) softmax + outputs
    softmax_kernel<<<BATCH, 256>>>(scoresp, cov, alphap, out);
    // (12) context vector
    {   dim3 grid(DH / 256, BATCH);  cimg_kernel<<<grid, 256>>>(gstarp, alphap, out); }
}

// round 11
// speedup vs baseline: 2.4935x; 1.0353x over previous
#include <cuda_runtime.h>
#include <cuda_bf16.h>
#include <cuda_fp16.h>
#include <cstdint>
#include <math.h>

#define GFD   4096
#define DH    1024
#define BATCH 32
#define TK    196
#define BT    (BATCH * TK)   // 6272

// Output layout in d_out (float): c_img[32,1024] | coverage_new[32,196,1] | alpha[32,196,1]
#define OUT_C      0
#define OUT_COV    (BATCH * DH)
#define OUT_ALPHA  (BATCH * DH + BT)

// ============================ scratch (__device__ globals) ============================
__device__ __align__(1024) __half g_WgF[GFD * GFD];    // Wg fp16 [GFD, GFD] row-major (K contiguous)
__device__ __align__(1024) __half g_GsTF[DH * GFD];    // Gs^T fp16 single [DH, GFD]
__device__ __align__(1024) __half g_W2TF[DH * GFD];    // W2^T fp16 single [DH, GFD]
__device__ __align__(1024) __half g_gfF[BT * GFD];     // gf fp16 single
__device__ __align__(1024) __half g_WgsTF[DH * DH];    // Wgs^T fp16 single [DH, DH]
__device__ __align__(1024) __half g_gsH[BT * DH];      // g_star fp16 hi
__device__ __align__(1024) __half g_gsL[BT * DH];      // g_star fp16 lo
__device__ float g_b2[DH];
__device__ float g_dec[BATCH * DH];
__device__ float g_scores[BT];
__device__ float g_alpha[BT];

// ============================ helpers ============================
__device__ __forceinline__ uint32_t smem_u32(const void* p) {
    uint32_t a;
    asm("{ .reg .u64 t; cvta.to.shared.u64 t, %1; cvt.u32.u64 %0, t; }" : "=r"(a) : "l"(p));
    return a;
}
__device__ __forceinline__ void ldsm4(uint32_t* r, uint32_t addr) {
    asm volatile("ldmatrix.sync.aligned.m8n8.x4.shared.b16 {%0,%1,%2,%3}, [%4];"
                 : "=r"(r[0]), "=r"(r[1]), "=r"(r[2]), "=r"(r[3]) : "r"(addr));
}
__device__ __forceinline__ void mma_h(float* c, const uint32_t* a, const uint32_t* b) {
    asm volatile("mma.sync.aligned.m16n8k16.row.col.f32.f16.f16.f32 "
                 "{%0,%1,%2,%3}, {%4,%5,%6,%7}, {%8,%9}, {%0,%1,%2,%3};"
                 : "+f"(c[0]), "+f"(c[1]), "+f"(c[2]), "+f"(c[3])
                 : "r"(a[0]), "r"(a[1]), "r"(a[2]), "r"(a[3]), "r"(b[0]), "r"(b[1]));
}
__device__ __forceinline__ uint32_t swz(uint32_t off) {   // SW128: bits[6:4] ^= bits[9:7]
    return off ^ ((off >> 3) & 0x70);
}

// ============================================================================
// WIDE 1-pass fp16 GEMM: C[M,N] = A@B^T. CTA tile 128x128x64, 128 thr (2x2 warps,
// warp tile 64x64), acc 128 f32/thread, double-buffered cp.async, 2 CTAs/SM.
// mode 3: outF16[m*ldc+n] = D (fp16)            (W2^T)
// mode 1: D += bias; emit fp16 hi/lo only       (g_star)
// ============================================================================
#define KTILE      64
#define W_TILE_B   16384                 // 128 rows x 128 B
#define W_STG_B    (2 * W_TILE_B)        // A + B = 32 KB
#define W_SM_A(s)  ((s) * W_STG_B)
#define W_SM_B(s)  ((s) * W_STG_B + W_TILE_B)
#define WIDE_SMEM  (2 * W_STG_B)         // 64 KB

__device__ __forceinline__ void issue_stage_w(
    uint32_t sb, int s, int kt, const char* A, const char* B,
    int K, int bm, int bn, int tid)
{
    const int k0 = kt * KTILE;
#pragma unroll
    for (int i = 0; i < 8; i++) {
        int idx = tid + i * 128;
        int r = idx >> 3, c = idx & 7;
        uint32_t so = swz((uint32_t)(r * 128 + c * 16));
        size_t goA = ((size_t)(bm + r) * K + k0 + c * 8) * 2;
        size_t goB = ((size_t)(bn + r) * K + k0 + c * 8) * 2;
        asm volatile("cp.async.cg.shared.global [%0], [%1], 16;" :: "r"(sb + W_SM_A(s) + so), "l"(A + goA) : "memory");
        asm volatile("cp.async.cg.shared.global [%0], [%1], 16;" :: "r"(sb + W_SM_B(s) + so), "l"(B + goB) : "memory");
    }
    asm volatile("cp.async.commit_group;" ::: "memory");
}

__global__ void __launch_bounds__(128, 2) gemm_wide(
    const void* A_, const void* B_,
    int K, int KT, int mode, int ldc,
    const float* __restrict__ bias,
    __half* __restrict__ outH, __half* __restrict__ outL,
    __half* __restrict__ outF16)
{
    extern __shared__ char smem[];
    const uint32_t sb = smem_u32(smem);
    const int tid = threadIdx.x;
    const int wid = tid >> 5, lane = tid & 31;
    const int wm = wid & 1, wn = wid >> 1;          // 2(m) x 2(n)
    const int bm = blockIdx.y * 128, bn = blockIdx.x * 128;
    const char* A = (const char*)A_;
    const char* B = (const char*)B_;

    float acc[4][8][4];
#pragma unroll
    for (int a = 0; a < 4; a++)
#pragma unroll
        for (int b = 0; b < 8; b++)
#pragma unroll
            for (int c = 0; c < 4; c++) acc[a][b][c] = 0.f;

    const uint32_t a_row  = (uint32_t)(wm * 64 + (lane & 15));                         // + mi*16
    const uint32_t a_kofs = (uint32_t)(((lane >> 4) & 1) * 16);                        // + kk*32
    const uint32_t b_row  = (uint32_t)(wn * 64 + (lane & 7) + ((lane >> 4) & 1) * 8);  // + nq*16
    const uint32_t b_kofs = (uint32_t)(((lane >> 3) & 1) * 16);                        // + kk*32

    issue_stage_w(sb, 0, 0, A, B, K, bm, bn, tid);

    for (int kt = 0; kt < KT; kt++) {
        const int s = kt & 1;
        if (kt + 1 < KT) {
            issue_stage_w(sb, s ^ 1, kt + 1, A, B, K, bm, bn, tid);
            asm volatile("cp.async.wait_group 1;" ::: "memory");
        } else {
            asm volatile("cp.async.wait_group 0;" ::: "memory");
        }
        __syncthreads();

        const uint32_t aS = sb + W_SM_A(s), bS = sb + W_SM_B(s);
#pragma unroll
        for (int kk = 0; kk < 4; kk++) {
            uint32_t fA[4][4], fB[4][4];
#pragma unroll
            for (int mi = 0; mi < 4; mi++) {
                uint32_t off = swz((a_row + mi * 16) * 128 + kk * 32 + a_kofs);
                ldsm4(fA[mi], aS + off);
            }
#pragma unroll
            for (int nq = 0; nq < 4; nq++) {
                uint32_t off = swz((b_row + nq * 16) * 128 + kk * 32 + b_kofs);
                ldsm4(fB[nq], bS + off);
            }
#pragma unroll
            for (int mi = 0; mi < 4; mi++)
#pragma unroll
                for (int nt = 0; nt < 8; nt++)
                    mma_h(acc[mi][nt], fA[mi], &fB[nt >> 1][(nt & 1) * 2]);
        }
        __syncthreads();
    }

    // ---------------- epilogue ----------------
    const int g = lane >> 2, tig = lane & 3;
#pragma unroll
    for (int mi = 0; mi < 4; mi++) {
#pragma unroll
        for (int h = 0; h < 2; h++) {
            const int m = bm + wm * 64 + mi * 16 + g + h * 8;
#pragma unroll
            for (int nt = 0; nt < 8; nt++) {
                const int n = bn + wn * 64 + nt * 8 + 2 * tig;
                float x0 = acc[mi][nt][h * 2 + 0];
                float x1 = acc[mi][nt][h * 2 + 1];
                if (mode == 3) {
                    *(__half2*)&outF16[(size_t)m * ldc + n] = __floats2half2_rn(x0, x1);
                } else {   // mode 1
                    x0 += bias[n];  x1 += bias[n + 1];
                    __half h0 = __float2half_rn(x0), h1 = __float2half_rn(x1);
                    *(__half2*)&outH[(size_t)m * ldc + n] = __halves2half2(h0, h1);
                    *(__half2*)&outL[(size_t)m * ldc + n] = __halves2half2(
                        __float2half_rn(x0 - __half2float(h0)),
                        __float2half_rn(x1 - __half2float(h1)));
                }
            }
        }
    }
}

// ============================================================================
// NARROW 2-pass fp16 GEMM (GEMM3): C = Ah@B^T + Al@B^T, fused scores epilogue.
// CTA tile 128x64x64, 128 thr (2x2 warps, warp tile 64x32), 2 CTAs/SM.
// ============================================================================
#define A_TILE_B  16384
#define B_TILE_B  8192
#define STG_B     (2 * A_TILE_B + B_TILE_B)       // AH AL BH = 40 KB
#define SM_AH(s)  ((s) * STG_B)
#define SM_AL(s)  (SM_AH(s) + A_TILE_B)
#define SM_BH(s)  (SM_AH(s) + 2 * A_TILE_B)
#define GEMM_SMEM (2 * STG_B)                     // 80 KB

__device__ __forceinline__ void issue_stage_n(
    uint32_t sb, int s, int kt,
    const char* Ah, const char* Al, const char* Bh,
    int K, int bm, int bn, int tid)
{
    const int k0 = kt * KTILE;
#pragma unroll
    for (int i = 0; i < 8; i++) {
        int idx = tid + i * 128;
        int r = idx >> 3, c = idx & 7;
        uint32_t so = swz((uint32_t)(r * 128 + c * 16));
        size_t go = ((size_t)(bm + r) * K + k0 + c * 8) * 2;
        asm volatile("cp.async.cg.shared.global [%0], [%1], 16;" :: "r"(sb + SM_AH(s) + so), "l"(Ah + go) : "memory");
        asm volatile("cp.async.cg.shared.global [%0], [%1], 16;" :: "r"(sb + SM_AL(s) + so), "l"(Al + go) : "memory");
    }
#pragma unroll
    for (int i = 0; i < 4; i++) {
        int idx = tid + i * 128;
        int r = idx >> 3, c = idx & 7;
        uint32_t so = swz((uint32_t)(r * 128 + c * 16));
        size_t go = ((size_t)(bn + r) * K + k0 + c * 8) * 2;
        asm volatile("cp.async.cg.shared.global [%0], [%1], 16;" :: "r"(sb + SM_BH(s) + so), "l"(Bh + go) : "memory");
    }
    asm volatile("cp.async.commit_group;" ::: "memory");
}

__global__ void __launch_bounds__(128, 2) gemm_scores(
    const void* Ah_, const void* Al_, const void* Bh_,
    int K, int KT,
    const float* __restrict__ dec, const float* __restrict__ cov,
    const float* __restrict__ v, float* __restrict__ scores)
{
    extern __shared__ char smem[];
    const uint32_t sb = smem_u32(smem);
    const int tid = threadIdx.x;
    const int wid = tid >> 5, lane = tid & 31;
    const int wm = wid & 1, wn = wid >> 1;
    const int bm = blockIdx.y * 128, bn = blockIdx.x * 64;
    const char* Ah = (const char*)Ah_;  const char* Al = (const char*)Al_;
    const char* Bh = (const char*)Bh_;

    float acc[4][4][4];
#pragma unroll
    for (int a = 0; a < 4; a++)
#pragma unroll
        for (int b = 0; b < 4; b++)
#pragma unroll
            for (int c = 0; c < 4; c++) acc[a][b][c] = 0.f;

    const uint32_t a_row  = (uint32_t)(wm * 64 + (lane & 15));
    const uint32_t a_kofs = (uint32_t)(((lane >> 4) & 1) * 16);
    const uint32_t b_row  = (uint32_t)(wn * 32 + (lane & 7) + ((lane >> 4) & 1) * 8);
    const uint32_t b_kofs = (uint32_t)(((lane >> 3) & 1) * 16);

    issue_stage_n(sb, 0, 0, Ah, Al, Bh, K, bm, bn, tid);

    for (int kt = 0; kt < KT; kt++) {
        const int s = kt & 1;
        if (kt + 1 < KT) {
            issue_stage_n(sb, s ^ 1, kt + 1, Ah, Al, Bh, K, bm, bn, tid);
            asm volatile("cp.async.wait_group 1;" ::: "memory");
        } else {
            asm volatile("cp.async.wait_group 0;" ::: "memory");
        }
        __syncthreads();

        const uint32_t aH = sb + SM_AH(s), aL = sb + SM_AL(s), bH = sb + SM_BH(s);
#pragma unroll
        for (int kk = 0; kk < 4; kk++) {
            uint32_t fAh[4][4], fAl[4][4], fBh[2][4];
#pragma unroll
            for (int mi = 0; mi < 4; mi++) {
                uint32_t off = swz((a_row + mi * 16) * 128 + kk * 32 + a_kofs);
                ldsm4(fAh[mi], aH + off);
            }
#pragma unroll
            for (int nq = 0; nq < 2; nq++) {
                uint32_t off = swz((b_row + nq * 16) * 128 + kk * 32 + b_kofs);
                ldsm4(fBh[nq], bH + off);
            }
#pragma unroll
            for (int mi = 0; mi < 4; mi++)
#pragma unroll
                for (int nt = 0; nt < 4; nt++)
                    mma_h(acc[mi][nt], fAh[mi], &fBh[nt >> 1][(nt & 1) * 2]);
#pragma unroll
            for (int mi = 0; mi < 4; mi++) {
                uint32_t off = swz((a_row + mi * 16) * 128 + kk * 32 + a_kofs);
                ldsm4(fAl[mi], aL + off);
            }
#pragma unroll
            for (int mi = 0; mi < 4; mi++)
#pragma unroll
                for (int nt = 0; nt < 4; nt++)
                    mma_h(acc[mi][nt], fAl[mi], &fBh[nt >> 1][(nt & 1) * 2]);
        }
        __syncthreads();
    }

    const int g = lane >> 2, tig = lane & 3;
#pragma unroll
    for (int mi = 0; mi < 4; mi++) {
#pragma unroll
        for (int h = 0; h < 2; h++) {
            const int m = bm + wm * 64 + mi * 16 + g + h * 8;
            const float cv = cov[m];
            const int bofs = (m / TK) * DH;
            float rsum = 0.f;
#pragma unroll
            for (int nt = 0; nt < 4; nt++) {
                const int n = bn + wn * 32 + nt * 8 + 2 * tig;
                rsum += tanhf(acc[mi][nt][h * 2 + 0] + dec[bofs + n] + cv) * v[n];
                rsum += tanhf(acc[mi][nt][h * 2 + 1] + dec[bofs + n + 1] + cv) * v[n + 1];
            }
            rsum += __shfl_xor_sync(0xffffffffu, rsum, 1);
            rsum += __shfl_xor_sync(0xffffffffu, rsum, 2);
            if (tig == 0) atomicAdd(&scores[m], rsum);
        }
    }
}

// ============================ conversion kernels ============================
__global__ void __launch_bounds__(256) csingle_h(
    const float4* __restrict__ in, __half2* __restrict__ oh, int n4)
{
    int i = blockIdx.x * 256 + threadIdx.x;
    if (i >= n4) return;
    float4 x = in[i];
    oh[2 * i]     = __floats2half2_rn(x.x, x.y);
    oh[2 * i + 1] = __floats2half2_rn(x.z, x.w);
}

__global__ void __launch_bounds__(256) tconv_h1(
    const float* __restrict__ in, __half* __restrict__ oh, int R, int C)
{
    __shared__ float t[32][33];
    const int bx = blockIdx.x * 32, by = blockIdx.y * 32;
    const int x = threadIdx.x & 31, y = threadIdx.x >> 5;
#pragma unroll
    for (int i = 0; i < 32; i += 8)
        t[y + i][x] = in[(size_t)(by + y + i) * C + bx + x];
    __syncthreads();
#pragma unroll
    for (int i = 0; i < 32; i += 8) {
        float val = t[x][y + i];
        oh[(size_t)(bx + y + i) * R + by + x] = __float2half_rn(val);
    }
}

// ============================ small kernels ============================
__global__ void __launch_bounds__(256) b2_kernel(
    const float* __restrict__ bg, const float* __restrict__ Gs,
    const float* __restrict__ bgs, float* __restrict__ b2)
{
    const int j  = blockIdx.x * 256 + threadIdx.x;
    const int k0 = blockIdx.y * 512;
    float s = 0.f;
#pragma unroll 8
    for (int i = 0; i < 512; i++)
        s += bg[k0 + i] * Gs[(size_t)(k0 + i) * DH + j];
    if (blockIdx.y == 0) s += bgs[j];
    atomicAdd(&b2[j], s);
}

__global__ void __launch_bounds__(256) dec_kernel(
    const float* __restrict__ s_t_hat, const float* __restrict__ Wdec,
    const float* __restrict__ bdec, float* __restrict__ dec)
{
    const int idx = blockIdx.x * 256 + threadIdx.x;
    const int b = idx >> 10, j = idx & (DH - 1);
    float s = bdec[j];
#pragma unroll 8
    for (int k = 0; k < DH; k++) s += s_t_hat[b * DH + k] * Wdec[(size_t)k * DH + j];
    dec[idx] = s;
}

__global__ void __launch_bounds__(256) softmax_kernel(
    const float* __restrict__ scores, const float* __restrict__ cov,
    float* __restrict__ alpha, float* __restrict__ out)
{
    const int b = blockIdx.x, t = threadIdx.x;
    __shared__ float red[8];
    __shared__ float smax, ssum;
    float sv = (t < TK) ? scores[b * TK + t] : -3.4e38f;

    float m = sv;
#pragma unroll
    for (int o = 16; o > 0; o >>= 1) m = fmaxf(m, __shfl_xor_sync(0xffffffffu, m, o));
    if ((t & 31) == 0) red[t >> 5] = m;
    __syncthreads();
    if (t < 8) {
        m = red[t];
#pragma unroll
        for (int o = 4; o > 0; o >>= 1) m = fmaxf(m, __shfl_xor_sync(0xffu, m, o));
        if (t == 0) smax = m;
    }
    __syncthreads();

    float e = (t < TK) ? expf(sv - smax) : 0.f;
    float su = e;
#pragma unroll
    for (int o = 16; o > 0; o >>= 1) su += __shfl_xor_sync(0xffffffffu, su, o);
    if ((t & 31) == 0) red[t >> 5] = su;
    __syncthreads();
    if (t < 8) {
        su = red[t];
#pragma unroll
        for (int o = 4; o > 0; o >>= 1) su += __shfl_xor_sync(0xffu, su, o);
        if (t == 0) ssum = su;
    }
    __syncthreads();

    if (t < TK) {
        const float a = e / ssum;
        alpha[b * TK + t] = a;
        out[OUT_ALPHA + b * TK + t] = a;
        out[OUT_COV + b * TK + t] = cov[b * TK + t] + a;
    }
}

// c_img from fp16 hi/lo reconstruction of g_star
__global__ void __launch_bounds__(256) cimg_kernel(
    const __half* __restrict__ gsH, const __half* __restrict__ gsL,
    const float* __restrict__ alpha, float* __restrict__ out)
{
    const int b = blockIdx.y;
    const int d = blockIdx.x * 256 + threadIdx.x;
    __shared__ float sal[TK];
    if (threadIdx.x < TK) sal[threadIdx.x] = alpha[b * TK + threadIdx.x];
    __syncthreads();
    float s = 0.f;
#pragma unroll 4
    for (int t = 0; t < TK; t++) {
        size_t idx = ((size_t)(b * TK + t)) * DH + d;
        s += sal[t] * (__half2float(gsH[idx]) + __half2float(gsL[idx]));
    }
    out[OUT_C + b * DH + d] = s;
}

// ============================ launch ============================
extern "C" void kernel_launch(void* const* d_in, const int* in_sizes, int n_in,
                              void* d_out, int out_size)
{
    const float* gf   = (const float*)d_in[0];
    const float* sth  = (const float*)d_in[1];
    const float* cov  = (const float*)d_in[2];
    const float* Wg   = (const float*)d_in[3];
    const float* bg   = (const float*)d_in[4];
    const float* Gs   = (const float*)d_in[5];
    const float* bgs  = (const float*)d_in[6];
    const float* Wgs  = (const float*)d_in[7];
    const float* Wdec = (const float*)d_in[8];
    const float* bdec = (const float*)d_in[9];
    const float* v    = (const float*)d_in[10];
    float* out = (float*)d_out;

    __half *WgF, *GsTF, *W2TF, *gfF, *WgsTF, *gsH, *gsL;
    float *b2p, *decp, *scoresp, *alphap;
    cudaGetSymbolAddress((void**)&WgF, g_WgF);
    cudaGetSymbolAddress((void**)&GsTF, g_GsTF);
    cudaGetSymbolAddress((void**)&W2TF, g_W2TF);
    cudaGetSymbolAddress((void**)&gfF, g_gfF);
    cudaGetSymbolAddress((void**)&WgsTF, g_WgsTF);
    cudaGetSymbolAddress((void**)&gsH, g_gsH);     cudaGetSymbolAddress((void**)&gsL, g_gsL);
    cudaGetSymbolAddress((void**)&b2p, g_b2);      cudaGetSymbolAddress((void**)&decp, g_dec);
    cudaGetSymbolAddress((void**)&scoresp, g_scores);
    cudaGetSymbolAddress((void**)&alphap, g_alpha);

    cudaFuncSetAttribute(gemm_wide,   cudaFuncAttributeMaxDynamicSharedMemorySize, WIDE_SMEM);
    cudaFuncSetAttribute(gemm_scores, cudaFuncAttributeMaxDynamicSharedMemorySize, GEMM_SMEM);

    // ---- single stream; slot 5 (ncu capture) = GEMM1 (wide) ----
    // (0) zero b2
    cudaMemsetAsync(b2p, 0, DH * sizeof(float));
    // (1) Wg -> fp16 single
    csingle_h<<<(GFD * GFD / 4 + 255) / 256, 256>>>((const float4*)Wg, (__half2*)WgF, GFD * GFD / 4);
    // (2) Gs -> Gs^T fp16 single
    {   dim3 g(DH / 32, GFD / 32);  tconv_h1<<<g, 256>>>(Gs, GsTF, GFD, DH); }
    // (3) b2 = bg @ Gs + bgs
    {   dim3 g(DH / 256, 8);  b2_kernel<<<g, 256>>>(bg, Gs, bgs, b2p); }
    // (4) zero scores
    cudaMemsetAsync(scoresp, 0, BT * sizeof(float));
    // (5) GEMM1 (wide 1-pass): W2T[DH,GFD] = GsT @ Wg^T -> fp16, ldc=GFD
    {
        dim3 grid(GFD / 128, DH / 128);
        gemm_wide<<<grid, 128, WIDE_SMEM>>>(GsTF, WgF, GFD, GFD / KTILE, 3, GFD,
            nullptr, nullptr, nullptr, W2TF);
    }
    // (6) gf -> fp16 single
    csingle_h<<<(BT * GFD / 4 + 255) / 256, 256>>>((const float4*)gf, (__half2*)gfF, BT * GFD / 4);
    // (7) Wgs -> Wgs^T fp16 single
    {   dim3 g(DH / 32, DH / 32);  tconv_h1<<<g, 256>>>(Wgs, WgsTF, DH, DH); }
    // (8) dec = s_t_hat @ Wdec + bdec
    dec_kernel<<<(BATCH * DH) / 256, 256>>>(sth, Wdec, bdec, decp);
    // (9) GEMM2 (wide 1-pass): g_star = gf @ W2 + b2 -> fp16 hi/lo, ldc=DH
    {
        dim3 grid(DH / 128, BT / 128);
        gemm_wide<<<grid, 128, WIDE_SMEM>>>(gfF, W2TF, GFD, GFD / KTILE, 1, DH,
            b2p, gsH, gsL, nullptr);
    }
    // (10) GEMM3 (narrow 2-pass, fused): scores = tanh(g_star@Wgs + dec + cov) . v
    {
        dim3 grid(DH / 64, BT / 128);
        gemm_scores<<<grid, 128, GEMM_SMEM>>>(gsH, gsL, WgsTF, DH, DH / KTILE,
            decp, cov, v, scoresp);
    }
    // (11) softmax + outputs
    softmax_kernel<<<BATCH, 256>>>(scoresp, cov, alphap, out);
    // (12) context vector (reads fp16 hi/lo)
    {   dim3 grid(DH / 256, BATCH);  cimg_kernel<<<grid, 256>>>(gsH, gsL, alphap, out); }
}

// round 12
// speedup vs baseline: 2.6805x; 1.0750x over previous
#include <cuda_runtime.h>
#include <cuda_bf16.h>
#include <cuda_fp16.h>
#include <cstdint>
#include <math.h>

#define GFD   4096
#define DH    1024
#define BATCH 32
#define TK    196
#define BT    (BATCH * TK)   // 6272

// Output layout in d_out (float): c_img[32,1024] | coverage_new[32,196,1] | alpha[32,196,1]
#define OUT_C      0
#define OUT_COV    (BATCH * DH)
#define OUT_ALPHA  (BATCH * DH + BT)

// ============================ scratch (__device__ globals) ============================
__device__ __align__(1024) __half g_WgF[GFD * GFD];    // Wg fp16 [GFD, GFD] row-major (K contiguous)
__device__ __align__(1024) __half g_GsTF[DH * GFD];    // Gs^T fp16 single [DH, GFD]
__device__ __align__(1024) __half g_W2TF[DH * GFD];    // W2^T fp16 single [DH, GFD]
__device__ __align__(1024) __half g_gfF[BT * GFD];     // gf fp16 single
__device__ __align__(1024) __half g_WgsTF[DH * DH];    // Wgs^T fp16 single [DH, DH]
__device__ __align__(1024) __half g_gsH[BT * DH];      // g_star fp16 hi
__device__ __align__(1024) __half g_gsL[BT * DH];      // g_star fp16 lo (cimg only)
__device__ float g_b2[DH];
__device__ float g_dec[BATCH * DH];
__device__ float g_scores[BT];
__device__ float g_alpha[BT];

// ============================ helpers ============================
__device__ __forceinline__ uint32_t smem_u32(const void* p) {
    uint32_t a;
    asm("{ .reg .u64 t; cvta.to.shared.u64 t, %1; cvt.u32.u64 %0, t; }" : "=r"(a) : "l"(p));
    return a;
}
__device__ __forceinline__ void ldsm4(uint32_t* r, uint32_t addr) {
    asm volatile("ldmatrix.sync.aligned.m8n8.x4.shared.b16 {%0,%1,%2,%3}, [%4];"
                 : "=r"(r[0]), "=r"(r[1]), "=r"(r[2]), "=r"(r[3]) : "r"(addr));
}
__device__ __forceinline__ void mma_h(float* c, const uint32_t* a, const uint32_t* b) {
    asm volatile("mma.sync.aligned.m16n8k16.row.col.f32.f16.f16.f32 "
                 "{%0,%1,%2,%3}, {%4,%5,%6,%7}, {%8,%9}, {%0,%1,%2,%3};"
                 : "+f"(c[0]), "+f"(c[1]), "+f"(c[2]), "+f"(c[3])
                 : "r"(a[0]), "r"(a[1]), "r"(a[2]), "r"(a[3]), "r"(b[0]), "r"(b[1]));
}
__device__ __forceinline__ uint32_t swz(uint32_t off) {   // SW128: bits[6:4] ^= bits[9:7]
    return off ^ ((off >> 3) & 0x70);
}

// ============================================================================
// WIDE 1-pass fp16 GEMM: C[M,N] = A@B^T. CTA tile 128x128x64, 128 thr (2x2 warps,
// warp tile 64x64), acc 128 f32/thread, double-buffered cp.async, 2 CTAs/SM.
// mode 3: outF16[m*ldc+n] = D (fp16)            (W2^T)
// mode 1: D += bias; emit fp16 hi/lo only       (g_star)
// ============================================================================
#define KTILE      64
#define W_TILE_B   16384                 // 128 rows x 128 B
#define W_STG_B    (2 * W_TILE_B)        // A + B = 32 KB
#define W_SM_A(s)  ((s) * W_STG_B)
#define W_SM_B(s)  ((s) * W_STG_B + W_TILE_B)
#define WIDE_SMEM  (2 * W_STG_B)         // 64 KB

__device__ __forceinline__ void issue_stage_w(
    uint32_t sb, int s, int kt, const char* A, const char* B,
    int K, int bm, int bn, int tid)
{
    const int k0 = kt * KTILE;
#pragma unroll
    for (int i = 0; i < 8; i++) {
        int idx = tid + i * 128;
        int r = idx >> 3, c = idx & 7;
        uint32_t so = swz((uint32_t)(r * 128 + c * 16));
        size_t goA = ((size_t)(bm + r) * K + k0 + c * 8) * 2;
        size_t goB = ((size_t)(bn + r) * K + k0 + c * 8) * 2;
        asm volatile("cp.async.cg.shared.global [%0], [%1], 16;" :: "r"(sb + W_SM_A(s) + so), "l"(A + goA) : "memory");
        asm volatile("cp.async.cg.shared.global [%0], [%1], 16;" :: "r"(sb + W_SM_B(s) + so), "l"(B + goB) : "memory");
    }
    asm volatile("cp.async.commit_group;" ::: "memory");
}

__global__ void __launch_bounds__(128, 2) gemm_wide(
    const void* A_, const void* B_,
    int K, int KT, int mode, int ldc,
    const float* __restrict__ bias,
    __half* __restrict__ outH, __half* __restrict__ outL,
    __half* __restrict__ outF16)
{
    extern __shared__ char smem[];
    const uint32_t sb = smem_u32(smem);
    const int tid = threadIdx.x;
    const int wid = tid >> 5, lane = tid & 31;
    const int wm = wid & 1, wn = wid >> 1;          // 2(m) x 2(n)
    const int bm = blockIdx.y * 128, bn = blockIdx.x * 128;
    const char* A = (const char*)A_;
    const char* B = (const char*)B_;

    float acc[4][8][4];
#pragma unroll
    for (int a = 0; a < 4; a++)
#pragma unroll
        for (int b = 0; b < 8; b++)
#pragma unroll
            for (int c = 0; c < 4; c++) acc[a][b][c] = 0.f;

    const uint32_t a_row  = (uint32_t)(wm * 64 + (lane & 15));                         // + mi*16
    const uint32_t a_kofs = (uint32_t)(((lane >> 4) & 1) * 16);                        // + kk*32
    const uint32_t b_row  = (uint32_t)(wn * 64 + (lane & 7) + ((lane >> 4) & 1) * 8);  // + nq*16
    const uint32_t b_kofs = (uint32_t)(((lane >> 3) & 1) * 16);                        // + kk*32

    issue_stage_w(sb, 0, 0, A, B, K, bm, bn, tid);

    for (int kt = 0; kt < KT; kt++) {
        const int s = kt & 1;
        if (kt + 1 < KT) {
            issue_stage_w(sb, s ^ 1, kt + 1, A, B, K, bm, bn, tid);
            asm volatile("cp.async.wait_group 1;" ::: "memory");
        } else {
            asm volatile("cp.async.wait_group 0;" ::: "memory");
        }
        __syncthreads();

        const uint32_t aS = sb + W_SM_A(s), bS = sb + W_SM_B(s);
#pragma unroll
        for (int kk = 0; kk < 4; kk++) {
            uint32_t fA[4][4], fB[4][4];
#pragma unroll
            for (int mi = 0; mi < 4; mi++) {
                uint32_t off = swz((a_row + mi * 16) * 128 + kk * 32 + a_kofs);
                ldsm4(fA[mi], aS + off);
            }
#pragma unroll
            for (int nq = 0; nq < 4; nq++) {
                uint32_t off = swz((b_row + nq * 16) * 128 + kk * 32 + b_kofs);
                ldsm4(fB[nq], bS + off);
            }
#pragma unroll
            for (int mi = 0; mi < 4; mi++)
#pragma unroll
                for (int nt = 0; nt < 8; nt++)
                    mma_h(acc[mi][nt], fA[mi], &fB[nt >> 1][(nt & 1) * 2]);
        }
        __syncthreads();
    }

    // ---------------- epilogue ----------------
    const int g = lane >> 2, tig = lane & 3;
#pragma unroll
    for (int mi = 0; mi < 4; mi++) {
#pragma unroll
        for (int h = 0; h < 2; h++) {
            const int m = bm + wm * 64 + mi * 16 + g + h * 8;
#pragma unroll
            for (int nt = 0; nt < 8; nt++) {
                const int n = bn + wn * 64 + nt * 8 + 2 * tig;
                float x0 = acc[mi][nt][h * 2 + 0];
                float x1 = acc[mi][nt][h * 2 + 1];
                if (mode == 3) {
                    *(__half2*)&outF16[(size_t)m * ldc + n] = __floats2half2_rn(x0, x1);
                } else {   // mode 1
                    x0 += bias[n];  x1 += bias[n + 1];
                    __half h0 = __float2half_rn(x0), h1 = __float2half_rn(x1);
                    *(__half2*)&outH[(size_t)m * ldc + n] = __halves2half2(h0, h1);
                    *(__half2*)&outL[(size_t)m * ldc + n] = __halves2half2(
                        __float2half_rn(x0 - __half2float(h0)),
                        __float2half_rn(x1 - __half2float(h1)));
                }
            }
        }
    }
}

// ============================================================================
// NARROW 1-pass fp16 GEMM (GEMM3): C = A@B^T, fused scores epilogue.
// CTA tile 128x64x64, 128 thr (2x2 warps, warp tile 64x32), 2 CTAs/SM.
// ============================================================================
#define N_A_TILE_B  16384
#define N_B_TILE_B  8192
#define N_STG_B     (N_A_TILE_B + N_B_TILE_B)     // A + B = 24 KB
#define N_SM_A(s)   ((s) * N_STG_B)
#define N_SM_B(s)   ((s) * N_STG_B + N_A_TILE_B)
#define SCORES_SMEM (2 * N_STG_B)                 // 48 KB

__device__ __forceinline__ void issue_stage_n(
    uint32_t sb, int s, int kt,
    const char* A, const char* B,
    int K, int bm, int bn, int tid)
{
    const int k0 = kt * KTILE;
#pragma unroll
    for (int i = 0; i < 8; i++) {
        int idx = tid + i * 128;
        int r = idx >> 3, c = idx & 7;
        uint32_t so = swz((uint32_t)(r * 128 + c * 16));
        size_t go = ((size_t)(bm + r) * K + k0 + c * 8) * 2;
        asm volatile("cp.async.cg.shared.global [%0], [%1], 16;" :: "r"(sb + N_SM_A(s) + so), "l"(A + go) : "memory");
    }
#pragma unroll
    for (int i = 0; i < 4; i++) {
        int idx = tid + i * 128;
        int r = idx >> 3, c = idx & 7;
        uint32_t so = swz((uint32_t)(r * 128 + c * 16));
        size_t go = ((size_t)(bn + r) * K + k0 + c * 8) * 2;
        asm volatile("cp.async.cg.shared.global [%0], [%1], 16;" :: "r"(sb + N_SM_B(s) + so), "l"(B + go) : "memory");
    }
    asm volatile("cp.async.commit_group;" ::: "memory");
}

__global__ void __launch_bounds__(128, 2) gemm_scores(
    const void* A_, const void* B_,
    int K, int KT,
    const float* __restrict__ dec, const float* __restrict__ cov,
    const float* __restrict__ v, float* __restrict__ scores)
{
    extern __shared__ char smem[];
    const uint32_t sb = smem_u32(smem);
    const int tid = threadIdx.x;
    const int wid = tid >> 5, lane = tid & 31;
    const int wm = wid & 1, wn = wid >> 1;
    const int bm = blockIdx.y * 128, bn = blockIdx.x * 64;
    const char* A = (const char*)A_;
    const char* B = (const char*)B_;

    float acc[4][4][4];
#pragma unroll
    for (int a = 0; a < 4; a++)
#pragma unroll
        for (int b = 0; b < 4; b++)
#pragma unroll
            for (int c = 0; c < 4; c++) acc[a][b][c] = 0.f;

    const uint32_t a_row  = (uint32_t)(wm * 64 + (lane & 15));
    const uint32_t a_kofs = (uint32_t)(((lane >> 4) & 1) * 16);
    const uint32_t b_row  = (uint32_t)(wn * 32 + (lane & 7) + ((lane >> 4) & 1) * 8);
    const uint32_t b_kofs = (uint32_t)(((lane >> 3) & 1) * 16);

    issue_stage_n(sb, 0, 0, A, B, K, bm, bn, tid);

    for (int kt = 0; kt < KT; kt++) {
        const int s = kt & 1;
        if (kt + 1 < KT) {
            issue_stage_n(sb, s ^ 1, kt + 1, A, B, K, bm, bn, tid);
            asm volatile("cp.async.wait_group 1;" ::: "memory");
        } else {
            asm volatile("cp.async.wait_group 0;" ::: "memory");
        }
        __syncthreads();

        const uint32_t aS = sb + N_SM_A(s), bS = sb + N_SM_B(s);
#pragma unroll
        for (int kk = 0; kk < 4; kk++) {
            uint32_t fA[4][4], fB[2][4];
#pragma unroll
            for (int mi = 0; mi < 4; mi++) {
                uint32_t off = swz((a_row + mi * 16) * 128 + kk * 32 + a_kofs);
                ldsm4(fA[mi], aS + off);
            }
#pragma unroll
            for (int nq = 0; nq < 2; nq++) {
                uint32_t off = swz((b_row + nq * 16) * 128 + kk * 32 + b_kofs);
                ldsm4(fB[nq], bS + off);
            }
#pragma unroll
            for (int mi = 0; mi < 4; mi++)
#pragma unroll
                for (int nt = 0; nt < 4; nt++)
                    mma_h(acc[mi][nt], fA[mi], &fB[nt >> 1][(nt & 1) * 2]);
        }
        __syncthreads();
    }

    const int g = lane >> 2, tig = lane & 3;
#pragma unroll
    for (int mi = 0; mi < 4; mi++) {
#pragma unroll
        for (int h = 0; h < 2; h++) {
            const int m = bm + wm * 64 + mi * 16 + g + h * 8;
            const float cv = cov[m];
            const int bofs = (m / TK) * DH;
            float rsum = 0.f;
#pragma unroll
            for (int nt = 0; nt < 4; nt++) {
                const int n = bn + wn * 32 + nt * 8 + 2 * tig;
                rsum += tanhf(acc[mi][nt][h * 2 + 0] + dec[bofs + n] + cv) * v[n];
                rsum += tanhf(acc[mi][nt][h * 2 + 1] + dec[bofs + n + 1] + cv) * v[n + 1];
            }
            rsum += __shfl_xor_sync(0xffffffffu, rsum, 1);
            rsum += __shfl_xor_sync(0xffffffffu, rsum, 2);
            if (tig == 0) atomicAdd(&scores[m], rsum);
        }
    }
}

// ============================ conversion kernels ============================
__global__ void __launch_bounds__(256) csingle_h(
    const float4* __restrict__ in, __half2* __restrict__ oh, int n4)
{
    int i = blockIdx.x * 256 + threadIdx.x;
    if (i >= n4) return;
    float4 x = in[i];
    oh[2 * i]     = __floats2half2_rn(x.x, x.y);
    oh[2 * i + 1] = __floats2half2_rn(x.z, x.w);
}

__global__ void __launch_bounds__(256) tconv_h1(
    const float* __restrict__ in, __half* __restrict__ oh, int R, int C)
{
    __shared__ float t[32][33];
    const int bx = blockIdx.x * 32, by = blockIdx.y * 32;
    const int x = threadIdx.x & 31, y = threadIdx.x >> 5;
#pragma unroll
    for (int i = 0; i < 32; i += 8)
        t[y + i][x] = in[(size_t)(by + y + i) * C + bx + x];
    __syncthreads();
#pragma unroll
    for (int i = 0; i < 32; i += 8) {
        float val = t[x][y + i];
        oh[(size_t)(bx + y + i) * R + by + x] = __float2half_rn(val);
    }
}

// ============================ small kernels ============================
__global__ void __launch_bounds__(256) b2_kernel(
    const float* __restrict__ bg, const float* __restrict__ Gs,
    const float* __restrict__ bgs, float* __restrict__ b2)
{
    const int j  = blockIdx.x * 256 + threadIdx.x;
    const int k0 = blockIdx.y * 512;
    float s = 0.f;
#pragma unroll 8
    for (int i = 0; i < 512; i++)
        s += bg[k0 + i] * Gs[(size_t)(k0 + i) * DH + j];
    if (blockIdx.y == 0) s += bgs[j];
    atomicAdd(&b2[j], s);
}

__global__ void __launch_bounds__(256) dec_kernel(
    const float* __restrict__ s_t_hat, const float* __restrict__ Wdec,
    const float* __restrict__ bdec, float* __restrict__ dec)
{
    const int idx = blockIdx.x * 256 + threadIdx.x;
    const int b = idx >> 10, j = idx & (DH - 1);
    float s = bdec[j];
#pragma unroll 8
    for (int k = 0; k < DH; k++) s += s_t_hat[b * DH + k] * Wdec[(size_t)k * DH + j];
    dec[idx] = s;
}

__global__ void __launch_bounds__(256) softmax_kernel(
    const float* __restrict__ scores, const float* __restrict__ cov,
    float* __restrict__ alpha, float* __restrict__ out)
{
    const int b = blockIdx.x, t = threadIdx.x;
    __shared__ float red[8];
    __shared__ float smax, ssum;
    float sv = (t < TK) ? scores[b * TK + t] : -3.4e38f;

    float m = sv;
#pragma unroll
    for (int o = 16; o > 0; o >>= 1) m = fmaxf(m, __shfl_xor_sync(0xffffffffu, m, o));
    if ((t & 31) == 0) red[t >> 5] = m;
    __syncthreads();
    if (t < 8) {
        m = red[t];
#pragma unroll
        for (int o = 4; o > 0; o >>= 1) m = fmaxf(m, __shfl_xor_sync(0xffu, m, o));
        if (t == 0) smax = m;
    }
    __syncthreads();

    float e = (t < TK) ? expf(sv - smax) : 0.f;
    float su = e;
#pragma unroll
    for (int o = 16; o > 0; o >>= 1) su += __shfl_xor_sync(0xffffffffu, su, o);
    if ((t & 31) == 0) red[t >> 5] = su;
    __syncthreads();
    if (t < 8) {
        su = red[t];
#pragma unroll
        for (int o = 4; o > 0; o >>= 1) su += __shfl_xor_sync(0xffu, su, o);
        if (t == 0) ssum = su;
    }
    __syncthreads();

    if (t < TK) {
        const float a = e / ssum;
        alpha[b * TK + t] = a;
        out[OUT_ALPHA + b * TK + t] = a;
        out[OUT_COV + b * TK + t] = cov[b * TK + t] + a;
    }
}

// c_img from fp16 hi/lo reconstruction of g_star; half2-vectorized (2 cols/thread)
__global__ void __launch_bounds__(256) cimg_kernel(
    const __half2* __restrict__ gsH, const __half2* __restrict__ gsL,
    const float* __restrict__ alpha, float* __restrict__ out)
{
    const int b = blockIdx.y;
    const int d2 = blockIdx.x * 256 + threadIdx.x;   // half2 index: 0..DH/2-1
    __shared__ float sal[TK];
    if (threadIdx.x < TK) sal[threadIdx.x] = alpha[b * TK + threadIdx.x];
    __syncthreads();
    float s0 = 0.f, s1 = 0.f;
#pragma unroll 4
    for (int t = 0; t < TK; t++) {
        size_t idx = ((size_t)(b * TK + t)) * (DH / 2) + d2;
        float2 h = __half22float2(gsH[idx]);
        float2 l = __half22float2(gsL[idx]);
        s0 += sal[t] * (h.x + l.x);
        s1 += sal[t] * (h.y + l.y);
    }
    *(float2*)&out[OUT_C + b * DH + 2 * d2] = make_float2(s0, s1);
}

// ============================ launch ============================
extern "C" void kernel_launch(void* const* d_in, const int* in_sizes, int n_in,
                              void* d_out, int out_size)
{
    const float* gf   = (const float*)d_in[0];
    const float* sth  = (const float*)d_in[1];
    const float* cov  = (const float*)d_in[2];
    const float* Wg   = (const float*)d_in[3];
    const float* bg   = (const float*)d_in[4];
    const float* Gs   = (const float*)d_in[5];
    const float* bgs  = (const float*)d_in[6];
    const float* Wgs  = (const float*)d_in[7];
    const float* Wdec = (const float*)d_in[8];
    const float* bdec = (const float*)d_in[9];
    const float* v    = (const float*)d_in[10];
    float* out = (float*)d_out;

    __half *WgF, *GsTF, *W2TF, *gfF, *WgsTF, *gsH, *gsL;
    float *b2p, *decp, *scoresp, *alphap;
    cudaGetSymbolAddress((void**)&WgF, g_WgF);
    cudaGetSymbolAddress((void**)&GsTF, g_GsTF);
    cudaGetSymbolAddress((void**)&W2TF, g_W2TF);
    cudaGetSymbolAddress((void**)&gfF, g_gfF);
    cudaGetSymbolAddress((void**)&WgsTF, g_WgsTF);
    cudaGetSymbolAddress((void**)&gsH, g_gsH);     cudaGetSymbolAddress((void**)&gsL, g_gsL);
    cudaGetSymbolAddress((void**)&b2p, g_b2);      cudaGetSymbolAddress((void**)&decp, g_dec);
    cudaGetSymbolAddress((void**)&scoresp, g_scores);
    cudaGetSymbolAddress((void**)&alphap, g_alpha);

    cudaFuncSetAttribute(gemm_wide,   cudaFuncAttributeMaxDynamicSharedMemorySize, WIDE_SMEM);
    cudaFuncSetAttribute(gemm_scores, cudaFuncAttributeMaxDynamicSharedMemorySize, SCORES_SMEM);

    // ---- single stream; slot 5 (ncu capture) = GEMM1 (wide) ----
    // (0) zero b2
    cudaMemsetAsync(b2p, 0, DH * sizeof(float));
    // (1) Wg -> fp16 single
    csingle_h<<<(GFD * GFD / 4 + 255) / 256, 256>>>((const float4*)Wg, (__half2*)WgF, GFD * GFD / 4);
    // (2) Gs -> Gs^T fp16 single
    {   dim3 g(DH / 32, GFD / 32);  tconv_h1<<<g, 256>>>(Gs, GsTF, GFD, DH); }
    // (3) b2 = bg @ Gs + bgs
    {   dim3 g(DH / 256, 8);  b2_kernel<<<g, 256>>>(bg, Gs, bgs, b2p); }
    // (4) zero scores
    cudaMemsetAsync(scoresp, 0, BT * sizeof(float));
    // (5) GEMM1 (wide 1-pass): W2T[DH,GFD] = GsT @ Wg^T -> fp16, ldc=GFD
    {
        dim3 grid(GFD / 128, DH / 128);
        gemm_wide<<<grid, 128, WIDE_SMEM>>>(GsTF, WgF, GFD, GFD / KTILE, 3, GFD,
            nullptr, nullptr, nullptr, W2TF);
    }
    // (6) gf -> fp16 single
    csingle_h<<<(BT * GFD / 4 + 255) / 256, 256>>>((const float4*)gf, (__half2*)gfF, BT * GFD / 4);
    // (7) Wgs -> Wgs^T fp16 single
    {   dim3 g(DH / 32, DH / 32);  tconv_h1<<<g, 256>>>(Wgs, WgsTF, DH, DH); }
    // (8) dec = s_t_hat @ Wdec + bdec
    dec_kernel<<<(BATCH * DH) / 256, 256>>>(sth, Wdec, bdec, decp);
    // (9) GEMM2 (wide 1-pass): g_star = gf @ W2 + b2 -> fp16 hi/lo, ldc=DH
    {
        dim3 grid(DH / 128, BT / 128);
        gemm_wide<<<grid, 128, WIDE_SMEM>>>(gfF, W2TF, GFD, GFD / KTILE, 1, DH,
            b2p, gsH, gsL, nullptr);
    }
    // (10) GEMM3 (narrow 1-pass, fused): scores = tanh(gsH@Wgs + dec + cov) . v
    {
        dim3 grid(DH / 64, BT / 128);
        gemm_scores<<<grid, 128, SCORES_SMEM>>>(gsH, WgsTF, DH, DH / KTILE,
            decp, cov, v, scoresp);
    }
    // (11) softmax + outputs
    softmax_kernel<<<BATCH, 256>>>(scoresp, cov, alphap, out);
    // (12) context vector (reads fp16 hi/lo, half2-vectorized)
    {   dim3 grid(DH / 512, BATCH);  cimg_kernel<<<grid, 256>>>((const __half2*)gsH, (const __half2*)gsL, alphap, out); }
}

// round 13
// speedup vs baseline: 2.8135x; 1.0496x over previous
#include <cuda_runtime.h>
#include <cuda_bf16.h>
#include <cuda_fp16.h>
#include <cstdint>
#include <math.h>

#define GFD   4096
#define DH    1024
#define BATCH 32
#define TK    196
#define BT    (BATCH * TK)   // 6272

// Output layout in d_out (float): c_img[32,1024] | coverage_new[32,196,1] | alpha[32,196,1]
#define OUT_C      0
#define OUT_COV    (BATCH * DH)
#define OUT_ALPHA  (BATCH * DH + BT)

// ============================ scratch (__device__ globals) ============================
__device__ __align__(1024) __half g_WgF[GFD * GFD];    // Wg fp16 [GFD, GFD] row-major (K contiguous)
__device__ __align__(1024) __half g_GsTF[DH * GFD];    // Gs^T fp16 single [DH, GFD]
__device__ __align__(1024) __half g_W2TF[DH * GFD];    // W2^T fp16 single [DH, GFD]
__device__ __align__(1024) __half g_gfF[BT * GFD];     // gf fp16 single
__device__ __align__(1024) __half g_WgsTF[DH * DH];    // Wgs^T fp16 single [DH, DH]
__device__ __align__(1024) __half g_gsH[BT * DH];      // g_star fp16 hi
__device__ __align__(1024) __half g_gsL[BT * DH];      // g_star fp16 lo (cimg only)
__device__ float g_b2[DH];
__device__ float g_dec[BATCH * DH];
__device__ float g_scores[BT];
__device__ float g_alpha[BT];

// ============================ helpers ============================
__device__ __forceinline__ uint32_t smem_u32(const void* p) {
    uint32_t a;
    asm("{ .reg .u64 t; cvta.to.shared.u64 t, %1; cvt.u32.u64 %0, t; }" : "=r"(a) : "l"(p));
    return a;
}
__device__ __forceinline__ void ldsm4(uint32_t* r, uint32_t addr) {
    asm volatile("ldmatrix.sync.aligned.m8n8.x4.shared.b16 {%0,%1,%2,%3}, [%4];"
                 : "=r"(r[0]), "=r"(r[1]), "=r"(r[2]), "=r"(r[3]) : "r"(addr));
}
__device__ __forceinline__ void mma_h(float* c, const uint32_t* a, const uint32_t* b) {
    asm volatile("mma.sync.aligned.m16n8k16.row.col.f32.f16.f16.f32 "
                 "{%0,%1,%2,%3}, {%4,%5,%6,%7}, {%8,%9}, {%0,%1,%2,%3};"
                 : "+f"(c[0]), "+f"(c[1]), "+f"(c[2]), "+f"(c[3])
                 : "r"(a[0]), "r"(a[1]), "r"(a[2]), "r"(a[3]), "r"(b[0]), "r"(b[1]));
}
__device__ __forceinline__ uint32_t swz(uint32_t off) {   // SW128: bits[6:4] ^= bits[9:7]
    return off ^ ((off >> 3) & 0x70);
}

// ============================================================================
// WIDE 1-pass fp16 GEMM: C[M,N] = A@B^T. CTA tile 128x128x64, 128 thr (2x2 warps,
// warp tile 64x64), acc 128 f32/thread, double-buffered cp.async, 2 CTAs/SM.
// mode 3: outF16[m*ldc+n] = D (fp16)            (W2^T)
// mode 1: D += bias; emit fp16 hi/lo only       (g_star)
// ============================================================================
#define KTILE      64
#define W_TILE_B   16384                 // 128 rows x 128 B
#define W_STG_B    (2 * W_TILE_B)        // A + B = 32 KB
#define W_SM_A(s)  ((s) * W_STG_B)
#define W_SM_B(s)  ((s) * W_STG_B + W_TILE_B)
#define WIDE_SMEM  (2 * W_STG_B)         // 64 KB

__device__ __forceinline__ void issue_stage_w(
    uint32_t sb, int s, int kt, const char* A, const char* B,
    int K, int bm, int bn, int tid)
{
    const int k0 = kt * KTILE;
#pragma unroll
    for (int i = 0; i < 8; i++) {
        int idx = tid + i * 128;
        int r = idx >> 3, c = idx & 7;
        uint32_t so = swz((uint32_t)(r * 128 + c * 16));
        size_t goA = ((size_t)(bm + r) * K + k0 + c * 8) * 2;
        size_t goB = ((size_t)(bn + r) * K + k0 + c * 8) * 2;
        asm volatile("cp.async.cg.shared.global [%0], [%1], 16;" :: "r"(sb + W_SM_A(s) + so), "l"(A + goA) : "memory");
        asm volatile("cp.async.cg.shared.global [%0], [%1], 16;" :: "r"(sb + W_SM_B(s) + so), "l"(B + goB) : "memory");
    }
    asm volatile("cp.async.commit_group;" ::: "memory");
}

__global__ void __launch_bounds__(128, 2) gemm_wide(
    const void* A_, const void* B_,
    int K, int KT, int mode, int ldc,
    const float* __restrict__ bias,
    __half* __restrict__ outH, __half* __restrict__ outL,
    __half* __restrict__ outF16)
{
    extern __shared__ char smem[];
    const uint32_t sb = smem_u32(smem);
    const int tid = threadIdx.x;
    const int wid = tid >> 5, lane = tid & 31;
    const int wm = wid & 1, wn = wid >> 1;          // 2(m) x 2(n)
    const int bm = blockIdx.y * 128, bn = blockIdx.x * 128;
    const char* A = (const char*)A_;
    const char* B = (const char*)B_;

    float acc[4][8][4];
#pragma unroll
    for (int a = 0; a < 4; a++)
#pragma unroll
        for (int b = 0; b < 8; b++)
#pragma unroll
            for (int c = 0; c < 4; c++) acc[a][b][c] = 0.f;

    const uint32_t a_row  = (uint32_t)(wm * 64 + (lane & 15));                         // + mi*16
    const uint32_t a_kofs = (uint32_t)(((lane >> 4) & 1) * 16);                        // + kk*32
    const uint32_t b_row  = (uint32_t)(wn * 64 + (lane & 7) + ((lane >> 4) & 1) * 8);  // + nq*16
    const uint32_t b_kofs = (uint32_t)(((lane >> 3) & 1) * 16);                        // + kk*32

    issue_stage_w(sb, 0, 0, A, B, K, bm, bn, tid);

    for (int kt = 0; kt < KT; kt++) {
        const int s = kt & 1;
        if (kt + 1 < KT) {
            issue_stage_w(sb, s ^ 1, kt + 1, A, B, K, bm, bn, tid);
            asm volatile("cp.async.wait_group 1;" ::: "memory");
        } else {
            asm volatile("cp.async.wait_group 0;" ::: "memory");
        }
        __syncthreads();

        const uint32_t aS = sb + W_SM_A(s), bS = sb + W_SM_B(s);
#pragma unroll
        for (int kk = 0; kk < 4; kk++) {
            uint32_t fA[4][4], fB[4][4];
#pragma unroll
            for (int mi = 0; mi < 4; mi++) {
                uint32_t off = swz((a_row + mi * 16) * 128 + kk * 32 + a_kofs);
                ldsm4(fA[mi], aS + off);
            }
#pragma unroll
            for (int nq = 0; nq < 4; nq++) {
                uint32_t off = swz((b_row + nq * 16) * 128 + kk * 32 + b_kofs);
                ldsm4(fB[nq], bS + off);
            }
#pragma unroll
            for (int mi = 0; mi < 4; mi++)
#pragma unroll
                for (int nt = 0; nt < 8; nt++)
                    mma_h(acc[mi][nt], fA[mi], &fB[nt >> 1][(nt & 1) * 2]);
        }
        __syncthreads();
    }

    // ---------------- epilogue ----------------
    const int g = lane >> 2, tig = lane & 3;
#pragma unroll
    for (int mi = 0; mi < 4; mi++) {
#pragma unroll
        for (int h = 0; h < 2; h++) {
            const int m = bm + wm * 64 + mi * 16 + g + h * 8;
#pragma unroll
            for (int nt = 0; nt < 8; nt++) {
                const int n = bn + wn * 64 + nt * 8 + 2 * tig;
                float x0 = acc[mi][nt][h * 2 + 0];
                float x1 = acc[mi][nt][h * 2 + 1];
                if (mode == 3) {
                    *(__half2*)&outF16[(size_t)m * ldc + n] = __floats2half2_rn(x0, x1);
                } else {   // mode 1
                    x0 += bias[n];  x1 += bias[n + 1];
                    __half h0 = __float2half_rn(x0), h1 = __float2half_rn(x1);
                    *(__half2*)&outH[(size_t)m * ldc + n] = __halves2half2(h0, h1);
                    *(__half2*)&outL[(size_t)m * ldc + n] = __halves2half2(
                        __float2half_rn(x0 - __half2float(h0)),
                        __float2half_rn(x1 - __half2float(h1)));
                }
            }
        }
    }
}

// ============================================================================
// NARROW 1-pass fp16 GEMM (GEMM3): C = A@B^T, fused scores epilogue.
// CTA tile 128x64x64, 128 thr (2x2 warps, warp tile 64x32), 2 CTAs/SM.
// ============================================================================
#define N_A_TILE_B  16384
#define N_B_TILE_B  8192
#define N_STG_B     (N_A_TILE_B + N_B_TILE_B)     // A + B = 24 KB
#define N_SM_A(s)   ((s) * N_STG_B)
#define N_SM_B(s)   ((s) * N_STG_B + N_A_TILE_B)
#define SCORES_SMEM (2 * N_STG_B)                 // 48 KB

__device__ __forceinline__ void issue_stage_n(
    uint32_t sb, int s, int kt,
    const char* A, const char* B,
    int K, int bm, int bn, int tid)
{
    const int k0 = kt * KTILE;
#pragma unroll
    for (int i = 0; i < 8; i++) {
        int idx = tid + i * 128;
        int r = idx >> 3, c = idx & 7;
        uint32_t so = swz((uint32_t)(r * 128 + c * 16));
        size_t go = ((size_t)(bm + r) * K + k0 + c * 8) * 2;
        asm volatile("cp.async.cg.shared.global [%0], [%1], 16;" :: "r"(sb + N_SM_A(s) + so), "l"(A + go) : "memory");
    }
#pragma unroll
    for (int i = 0; i < 4; i++) {
        int idx = tid + i * 128;
        int r = idx >> 3, c = idx & 7;
        uint32_t so = swz((uint32_t)(r * 128 + c * 16));
        size_t go = ((size_t)(bn + r) * K + k0 + c * 8) * 2;
        asm volatile("cp.async.cg.shared.global [%0], [%1], 16;" :: "r"(sb + N_SM_B(s) + so), "l"(B + go) : "memory");
    }
    asm volatile("cp.async.commit_group;" ::: "memory");
}

__global__ void __launch_bounds__(128, 2) gemm_scores(
    const void* A_, const void* B_,
    int K, int KT,
    const float* __restrict__ dec, const float* __restrict__ cov,
    const float* __restrict__ v, float* __restrict__ scores)
{
    extern __shared__ char smem[];
    const uint32_t sb = smem_u32(smem);
    const int tid = threadIdx.x;
    const int wid = tid >> 5, lane = tid & 31;
    const int wm = wid & 1, wn = wid >> 1;
    const int bm = blockIdx.y * 128, bn = blockIdx.x * 64;
    const char* A = (const char*)A_;
    const char* B = (const char*)B_;

    float acc[4][4][4];
#pragma unroll
    for (int a = 0; a < 4; a++)
#pragma unroll
        for (int b = 0; b < 4; b++)
#pragma unroll
            for (int c = 0; c < 4; c++) acc[a][b][c] = 0.f;

    const uint32_t a_row  = (uint32_t)(wm * 64 + (lane & 15));
    const uint32_t a_kofs = (uint32_t)(((lane >> 4) & 1) * 16);
    const uint32_t b_row  = (uint32_t)(wn * 32 + (lane & 7) + ((lane >> 4) & 1) * 8);
    const uint32_t b_kofs = (uint32_t)(((lane >> 3) & 1) * 16);

    issue_stage_n(sb, 0, 0, A, B, K, bm, bn, tid);

    for (int kt = 0; kt < KT; kt++) {
        const int s = kt & 1;
        if (kt + 1 < KT) {
            issue_stage_n(sb, s ^ 1, kt + 1, A, B, K, bm, bn, tid);
            asm volatile("cp.async.wait_group 1;" ::: "memory");
        } else {
            asm volatile("cp.async.wait_group 0;" ::: "memory");
        }
        __syncthreads();

        const uint32_t aS = sb + N_SM_A(s), bS = sb + N_SM_B(s);
#pragma unroll
        for (int kk = 0; kk < 4; kk++) {
            uint32_t fA[4][4], fB[2][4];
#pragma unroll
            for (int mi = 0; mi < 4; mi++) {
                uint32_t off = swz((a_row + mi * 16) * 128 + kk * 32 + a_kofs);
                ldsm4(fA[mi], aS + off);
            }
#pragma unroll
            for (int nq = 0; nq < 2; nq++) {
                uint32_t off = swz((b_row + nq * 16) * 128 + kk * 32 + b_kofs);
                ldsm4(fB[nq], bS + off);
            }
#pragma unroll
            for (int mi = 0; mi < 4; mi++)
#pragma unroll
                for (int nt = 0; nt < 4; nt++)
                    mma_h(acc[mi][nt], fA[mi], &fB[nt >> 1][(nt & 1) * 2]);
        }
        __syncthreads();
    }

    const int g = lane >> 2, tig = lane & 3;
#pragma unroll
    for (int mi = 0; mi < 4; mi++) {
#pragma unroll
        for (int h = 0; h < 2; h++) {
            const int m = bm + wm * 64 + mi * 16 + g + h * 8;
            const float cv = cov[m];
            const int bofs = (m / TK) * DH;
            float rsum = 0.f;
#pragma unroll
            for (int nt = 0; nt < 4; nt++) {
                const int n = bn + wn * 32 + nt * 8 + 2 * tig;
                rsum += tanhf(acc[mi][nt][h * 2 + 0] + dec[bofs + n] + cv) * v[n];
                rsum += tanhf(acc[mi][nt][h * 2 + 1] + dec[bofs + n + 1] + cv) * v[n + 1];
            }
            rsum += __shfl_xor_sync(0xffffffffu, rsum, 1);
            rsum += __shfl_xor_sync(0xffffffffu, rsum, 2);
            if (tig == 0) atomicAdd(&scores[m], rsum);
        }
    }
}

// ============================ conversion kernels ============================
__global__ void __launch_bounds__(256) csingle_h(
    const float4* __restrict__ in, __half2* __restrict__ oh, int n4)
{
    int i = blockIdx.x * 256 + threadIdx.x;
    if (i >= n4) return;
    float4 x = in[i];
    oh[2 * i]     = __floats2half2_rn(x.x, x.y);
    oh[2 * i + 1] = __floats2half2_rn(x.z, x.w);
}

__global__ void __launch_bounds__(256) tconv_h1(
    const float* __restrict__ in, __half* __restrict__ oh, int R, int C)
{
    __shared__ float t[32][33];
    const int bx = blockIdx.x * 32, by = blockIdx.y * 32;
    const int x = threadIdx.x & 31, y = threadIdx.x >> 5;
#pragma unroll
    for (int i = 0; i < 32; i += 8)
        t[y + i][x] = in[(size_t)(by + y + i) * C + bx + x];
    __syncthreads();
#pragma unroll
    for (int i = 0; i < 32; i += 8) {
        float val = t[x][y + i];
        oh[(size_t)(bx + y + i) * R + by + x] = __float2half_rn(val);
    }
}

// ============================ small kernels ============================
__global__ void __launch_bounds__(256) b2_kernel(
    const float* __restrict__ bg, const float* __restrict__ Gs,
    const float* __restrict__ bgs, float* __restrict__ b2)
{
    const int j  = blockIdx.x * 256 + threadIdx.x;
    const int k0 = blockIdx.y * 512;
    float s = 0.f;
#pragma unroll 8
    for (int i = 0; i < 512; i++)
        s += bg[k0 + i] * Gs[(size_t)(k0 + i) * DH + j];
    if (blockIdx.y == 0) s += bgs[j];
    atomicAdd(&b2[j], s);
}

__global__ void __launch_bounds__(256) dec_kernel(
    const float* __restrict__ s_t_hat, const float* __restrict__ Wdec,
    const float* __restrict__ bdec, float* __restrict__ dec)
{
    const int idx = blockIdx.x * 256 + threadIdx.x;
    const int b = idx >> 10, j = idx & (DH - 1);
    float s = bdec[j];
#pragma unroll 8
    for (int k = 0; k < DH; k++) s += s_t_hat[b * DH + k] * Wdec[(size_t)k * DH + j];
    dec[idx] = s;
}

__global__ void __launch_bounds__(256) softmax_kernel(
    const float* __restrict__ scores, const float* __restrict__ cov,
    float* __restrict__ alpha, float* __restrict__ out)
{
    const int b = blockIdx.x, t = threadIdx.x;
    __shared__ float red[8];
    __shared__ float smax, ssum;
    float sv = (t < TK) ? scores[b * TK + t] : -3.4e38f;

    float m = sv;
#pragma unroll
    for (int o = 16; o > 0; o >>= 1) m = fmaxf(m, __shfl_xor_sync(0xffffffffu, m, o));
    if ((t & 31) == 0) red[t >> 5] = m;
    __syncthreads();
    if (t < 8) {
        m = red[t];
#pragma unroll
        for (int o = 4; o > 0; o >>= 1) m = fmaxf(m, __shfl_xor_sync(0xffu, m, o));
        if (t == 0) smax = m;
    }
    __syncthreads();

    float e = (t < TK) ? expf(sv - smax) : 0.f;
    float su = e;
#pragma unroll
    for (int o = 16; o > 0; o >>= 1) su += __shfl_xor_sync(0xffffffffu, su, o);
    if ((t & 31) == 0) red[t >> 5] = su;
    __syncthreads();
    if (t < 8) {
        su = red[t];
#pragma unroll
        for (int o = 4; o > 0; o >>= 1) su += __shfl_xor_sync(0xffu, su, o);
        if (t == 0) ssum = su;
    }
    __syncthreads();

    if (t < TK) {
        const float a = e / ssum;
        alpha[b * TK + t] = a;
        out[OUT_ALPHA + b * TK + t] = a;
        out[OUT_COV + b * TK + t] = cov[b * TK + t] + a;
    }
}

// c_img from fp16 hi/lo reconstruction of g_star; half2-vectorized (2 cols/thread)
__global__ void __launch_bounds__(256) cimg_kernel(
    const __half2* __restrict__ gsH, const __half2* __restrict__ gsL,
    const float* __restrict__ alpha, float* __restrict__ out)
{
    const int b = blockIdx.y;
    const int d2 = blockIdx.x * 256 + threadIdx.x;   // half2 index: 0..DH/2-1
    __shared__ float sal[TK];
    if (threadIdx.x < TK) sal[threadIdx.x] = alpha[b * TK + threadIdx.x];
    __syncthreads();
    float s0 = 0.f, s1 = 0.f;
#pragma unroll 4
    for (int t = 0; t < TK; t++) {
        size_t idx = ((size_t)(b * TK + t)) * (DH / 2) + d2;
        float2 h = __half22float2(gsH[idx]);
        float2 l = __half22float2(gsL[idx]);
        s0 += sal[t] * (h.x + l.x);
        s1 += sal[t] * (h.y + l.y);
    }
    *(float2*)&out[OUT_C + b * DH + 2 * d2] = make_float2(s0, s1);
}

// ============================ launch ============================
extern "C" void kernel_launch(void* const* d_in, const int* in_sizes, int n_in,
                              void* d_out, int out_size)
{
    const float* gf   = (const float*)d_in[0];
    const float* sth  = (const float*)d_in[1];
    const float* cov  = (const float*)d_in[2];
    const float* Wg   = (const float*)d_in[3];
    const float* bg   = (const float*)d_in[4];
    const float* Gs   = (const float*)d_in[5];
    const float* bgs  = (const float*)d_in[6];
    const float* Wgs  = (const float*)d_in[7];
    const float* Wdec = (const float*)d_in[8];
    const float* bdec = (const float*)d_in[9];
    const float* v    = (const float*)d_in[10];
    float* out = (float*)d_out;

    __half *WgF, *GsTF, *W2TF, *gfF, *WgsTF, *gsH, *gsL;
    float *b2p, *decp, *scoresp, *alphap;
    cudaGetSymbolAddress((void**)&WgF, g_WgF);
    cudaGetSymbolAddress((void**)&GsTF, g_GsTF);
    cudaGetSymbolAddress((void**)&W2TF, g_W2TF);
    cudaGetSymbolAddress((void**)&gfF, g_gfF);
    cudaGetSymbolAddress((void**)&WgsTF, g_WgsTF);
    cudaGetSymbolAddress((void**)&gsH, g_gsH);     cudaGetSymbolAddress((void**)&gsL, g_gsL);
    cudaGetSymbolAddress((void**)&b2p, g_b2);      cudaGetSymbolAddress((void**)&decp, g_dec);
    cudaGetSymbolAddress((void**)&scoresp, g_scores);
    cudaGetSymbolAddress((void**)&alphap, g_alpha);

    cudaFuncSetAttribute(gemm_wide,   cudaFuncAttributeMaxDynamicSharedMemorySize, WIDE_SMEM);
    cudaFuncSetAttribute(gemm_scores, cudaFuncAttributeMaxDynamicSharedMemorySize, SCORES_SMEM);

    // Side stream + events (created once; resources, not work)
    static cudaStream_t sideS = nullptr;
    static cudaEvent_t evFork = nullptr, evJoin = nullptr;
    if (sideS == nullptr) {
        cudaStreamCreateWithFlags(&sideS, cudaStreamNonBlocking);
        cudaEventCreateWithFlags(&evFork, cudaEventDisableTiming);
        cudaEventCreateWithFlags(&evJoin, cudaEventDisableTiming);
    }

    // ---- main: DRAM-bound conversions first (exclusive DRAM use) ----
    // (0) zero b2
    cudaMemsetAsync(b2p, 0, DH * sizeof(float));
    // (1) Wg -> fp16 single
    csingle_h<<<(GFD * GFD / 4 + 255) / 256, 256>>>((const float4*)Wg, (__half2*)WgF, GFD * GFD / 4);
    // (2) Gs -> Gs^T fp16 single
    {   dim3 g(DH / 32, GFD / 32);  tconv_h1<<<g, 256>>>(Gs, GsTF, GFD, DH); }
    // fork AFTER main's conversions: side work overlaps only with compute-bound GEMM1
    cudaEventRecord(evFork, 0);
    // (3) b2 = bg @ Gs + bgs
    {   dim3 g(DH / 256, 8);  b2_kernel<<<g, 256>>>(bg, Gs, bgs, b2p); }
    // (4) zero scores
    cudaMemsetAsync(scoresp, 0, BT * sizeof(float));
    // (5) GEMM1 (wide 1-pass): W2T[DH,GFD] = GsT @ Wg^T -> fp16, ldc=GFD
    {
        dim3 grid(GFD / 128, DH / 128);
        gemm_wide<<<grid, 128, WIDE_SMEM>>>(GsTF, WgF, GFD, GFD / KTILE, 3, GFD,
            nullptr, nullptr, nullptr, W2TF);
    }

    // ---- side: gf conversion + GEMM3 inputs, hidden under GEMM1 ----
    cudaStreamWaitEvent(sideS, evFork, 0);
    csingle_h<<<(BT * GFD / 4 + 255) / 256, 256, 0, sideS>>>((const float4*)gf,
        (__half2*)gfF, BT * GFD / 4);
    {   dim3 g(DH / 32, DH / 32);  tconv_h1<<<g, 256, 0, sideS>>>(Wgs, WgsTF, DH, DH); }
    dec_kernel<<<(BATCH * DH) / 256, 256, 0, sideS>>>(sth, Wdec, bdec, decp);
    cudaEventRecord(evJoin, sideS);

    // ---- main: join, then dependent GEMMs ----
    cudaStreamWaitEvent(0, evJoin, 0);
    // GEMM2 (wide 1-pass): g_star = gf @ W2 + b2 -> fp16 hi/lo, ldc=DH
    {
        dim3 grid(DH / 128, BT / 128);
        gemm_wide<<<grid, 128, WIDE_SMEM>>>(gfF, W2TF, GFD, GFD / KTILE, 1, DH,
            b2p, gsH, gsL, nullptr);
    }
    // GEMM3 (narrow 1-pass, fused): scores = tanh(gsH@Wgs + dec + cov) . v
    {
        dim3 grid(DH / 64, BT / 128);
        gemm_scores<<<grid, 128, SCORES_SMEM>>>(gsH, WgsTF, DH, DH / KTILE,
            decp, cov, v, scoresp);
    }
    // softmax + outputs
    softmax_kernel<<<BATCH, 256>>>(scoresp, cov, alphap, out);
    // context vector (reads fp16 hi/lo, half2-vectorized)
    {   dim3 grid(DH / 512, BATCH);  cimg_kernel<<<grid, 256>>>((const __half2*)gsH, (const __half2*)gsL, alphap, out); }
}

// round 14
// speedup vs baseline: 3.3575x; 1.1934x over previous
#include <cuda_runtime.h>
#include <cuda_bf16.h>
#include <cuda_fp16.h>
#include <cstdint>
#include <math.h>

#define GFD   4096
#define DH    1024
#define BATCH 32
#define TK    196
#define BT    (BATCH * TK)   // 6272

// Output layout in d_out (float): c_img[32,1024] | coverage_new[32,196,1] | alpha[32,196,1]
#define OUT_C      0
#define OUT_COV    (BATCH * DH)
#define OUT_ALPHA  (BATCH * DH + BT)

// ============================ scratch (__device__ globals) ============================
__device__ __align__(1024) __half g_WgF[GFD * GFD];    // Wg fp16 [GFD, GFD] row-major (K contiguous)
__device__ __align__(1024) __half g_GsTF[DH * GFD];    // Gs^T fp16 single [DH, GFD]
__device__ __align__(1024) __half g_W2TF[DH * GFD];    // W2^T fp16 single [DH, GFD]
__device__ __align__(1024) __half g_gfF[BT * GFD];     // gf fp16 single
__device__ __align__(1024) __half g_WgsTF[DH * DH];    // Wgs^T fp16 single [DH, DH]
__device__ __align__(1024) __half g_gsH[BT * DH];      // g_star fp16 hi
__device__ __align__(1024) __half g_gsL[BT * DH];      // g_star fp16 lo (cimg only)
__device__ float g_b2[DH];
__device__ float g_dec[BATCH * DH];
__device__ float g_scores[BT];
__device__ float g_alpha[BT];

// ============================ helpers ============================
__device__ __forceinline__ uint32_t smem_u32(const void* p) {
    uint32_t a;
    asm("{ .reg .u64 t; cvta.to.shared.u64 t, %1; cvt.u32.u64 %0, t; }" : "=r"(a) : "l"(p));
    return a;
}
__device__ __forceinline__ void ldsm4(uint32_t* r, uint32_t addr) {
    asm volatile("ldmatrix.sync.aligned.m8n8.x4.shared.b16 {%0,%1,%2,%3}, [%4];"
                 : "=r"(r[0]), "=r"(r[1]), "=r"(r[2]), "=r"(r[3]) : "r"(addr));
}
__device__ __forceinline__ void mma_h(float* c, const uint32_t* a, const uint32_t* b) {
    asm volatile("mma.sync.aligned.m16n8k16.row.col.f32.f16.f16.f32 "
                 "{%0,%1,%2,%3}, {%4,%5,%6,%7}, {%8,%9}, {%0,%1,%2,%3};"
                 : "+f"(c[0]), "+f"(c[1]), "+f"(c[2]), "+f"(c[3])
                 : "r"(a[0]), "r"(a[1]), "r"(a[2]), "r"(a[3]), "r"(b[0]), "r"(b[1]));
}
__device__ __forceinline__ uint32_t swz(uint32_t off) {   // SW128: bits[6:4] ^= bits[9:7]
    return off ^ ((off >> 3) & 0x70);
}

// ============================================================================
// WIDE 1-pass fp16 GEMM: C[M,N] = A@B^T. CTA tile 128x128x64, 128 thr (2x2 warps,
// warp tile 64x64), acc 128 f32/thread, double-buffered cp.async, 2 CTAs/SM.
// mode 3: outF16[m*ldc+n] = D (fp16)            (W2^T)
// mode 1: D += bias; emit fp16 hi/lo only       (g_star)
// ============================================================================
#define KTILE      64
#define W_TILE_B   16384                 // 128 rows x 128 B
#define W_STG_B    (2 * W_TILE_B)        // A + B = 32 KB
#define W_SM_A(s)  ((s) * W_STG_B)
#define W_SM_B(s)  ((s) * W_STG_B + W_TILE_B)
#define WIDE_SMEM  (2 * W_STG_B)         // 64 KB

__device__ __forceinline__ void issue_stage_w(
    uint32_t sb, int s, int kt, const char* A, const char* B,
    int K, int bm, int bn, int tid)
{
    const int k0 = kt * KTILE;
#pragma unroll
    for (int i = 0; i < 8; i++) {
        int idx = tid + i * 128;
        int r = idx >> 3, c = idx & 7;
        uint32_t so = swz((uint32_t)(r * 128 + c * 16));
        size_t goA = ((size_t)(bm + r) * K + k0 + c * 8) * 2;
        size_t goB = ((size_t)(bn + r) * K + k0 + c * 8) * 2;
        asm volatile("cp.async.cg.shared.global [%0], [%1], 16;" :: "r"(sb + W_SM_A(s) + so), "l"(A + goA) : "memory");
        asm volatile("cp.async.cg.shared.global [%0], [%1], 16;" :: "r"(sb + W_SM_B(s) + so), "l"(B + goB) : "memory");
    }
    asm volatile("cp.async.commit_group;" ::: "memory");
}

__global__ void __launch_bounds__(128, 2) gemm_wide(
    const void* A_, const void* B_,
    int K, int KT, int mode, int ldc,
    const float* __restrict__ bias,
    __half* __restrict__ outH, __half* __restrict__ outL,
    __half* __restrict__ outF16)
{
    extern __shared__ char smem[];
    const uint32_t sb = smem_u32(smem);
    const int tid = threadIdx.x;
    const int wid = tid >> 5, lane = tid & 31;
    const int wm = wid & 1, wn = wid >> 1;          // 2(m) x 2(n)
    const int bm = blockIdx.y * 128, bn = blockIdx.x * 128;
    const char* A = (const char*)A_;
    const char* B = (const char*)B_;

    float acc[4][8][4];
#pragma unroll
    for (int a = 0; a < 4; a++)
#pragma unroll
        for (int b = 0; b < 8; b++)
#pragma unroll
            for (int c = 0; c < 4; c++) acc[a][b][c] = 0.f;

    const uint32_t a_row  = (uint32_t)(wm * 64 + (lane & 15));                         // + mi*16
    const uint32_t a_kofs = (uint32_t)(((lane >> 4) & 1) * 16);                        // + kk*32
    const uint32_t b_row  = (uint32_t)(wn * 64 + (lane & 7) + ((lane >> 4) & 1) * 8);  // + nq*16
    const uint32_t b_kofs = (uint32_t)(((lane >> 3) & 1) * 16);                        // + kk*32

    issue_stage_w(sb, 0, 0, A, B, K, bm, bn, tid);

    for (int kt = 0; kt < KT; kt++) {
        const int s = kt & 1;
        if (kt + 1 < KT) {
            issue_stage_w(sb, s ^ 1, kt + 1, A, B, K, bm, bn, tid);
            asm volatile("cp.async.wait_group 1;" ::: "memory");
        } else {
            asm volatile("cp.async.wait_group 0;" ::: "memory");
        }
        __syncthreads();

        const uint32_t aS = sb + W_SM_A(s), bS = sb + W_SM_B(s);
#pragma unroll
        for (int kk = 0; kk < 4; kk++) {
            uint32_t fA[4][4], fB[4][4];
#pragma unroll
            for (int mi = 0; mi < 4; mi++) {
                uint32_t off = swz((a_row + mi * 16) * 128 + kk * 32 + a_kofs);
                ldsm4(fA[mi], aS + off);
            }
#pragma unroll
            for (int nq = 0; nq < 4; nq++) {
                uint32_t off = swz((b_row + nq * 16) * 128 + kk * 32 + b_kofs);
                ldsm4(fB[nq], bS + off);
            }
#pragma unroll
            for (int mi = 0; mi < 4; mi++)
#pragma unroll
                for (int nt = 0; nt < 8; nt++)
                    mma_h(acc[mi][nt], fA[mi], &fB[nt >> 1][(nt & 1) * 2]);
        }
        __syncthreads();
    }

    // ---------------- epilogue ----------------
    const int g = lane >> 2, tig = lane & 3;
#pragma unroll
    for (int mi = 0; mi < 4; mi++) {
#pragma unroll
        for (int h = 0; h < 2; h++) {
            const int m = bm + wm * 64 + mi * 16 + g + h * 8;
#pragma unroll
            for (int nt = 0; nt < 8; nt++) {
                const int n = bn + wn * 64 + nt * 8 + 2 * tig;
                float x0 = acc[mi][nt][h * 2 + 0];
                float x1 = acc[mi][nt][h * 2 + 1];
                if (mode == 3) {
                    *(__half2*)&outF16[(size_t)m * ldc + n] = __floats2half2_rn(x0, x1);
                } else {   // mode 1
                    x0 += bias[n];  x1 += bias[n + 1];
                    __half h0 = __float2half_rn(x0), h1 = __float2half_rn(x1);
                    *(__half2*)&outH[(size_t)m * ldc + n] = __halves2half2(h0, h1);
                    *(__half2*)&outL[(size_t)m * ldc + n] = __halves2half2(
                        __float2half_rn(x0 - __half2float(h0)),
                        __float2half_rn(x1 - __half2float(h1)));
                }
            }
        }
    }
}

// ============================================================================
// NARROW 1-pass fp16 GEMM (GEMM3): C = A@B^T, fused scores epilogue.
// CTA tile 128x64x64, 128 thr (2x2 warps, warp tile 64x32), 2 CTAs/SM.
// ============================================================================
#define N_A_TILE_B  16384
#define N_B_TILE_B  8192
#define N_STG_B     (N_A_TILE_B + N_B_TILE_B)     // A + B = 24 KB
#define N_SM_A(s)   ((s) * N_STG_B)
#define N_SM_B(s)   ((s) * N_STG_B + N_A_TILE_B)
#define SCORES_SMEM (2 * N_STG_B)                 // 48 KB

__device__ __forceinline__ void issue_stage_n(
    uint32_t sb, int s, int kt,
    const char* A, const char* B,
    int K, int bm, int bn, int tid)
{
    const int k0 = kt * KTILE;
#pragma unroll
    for (int i = 0; i < 8; i++) {
        int idx = tid + i * 128;
        int r = idx >> 3, c = idx & 7;
        uint32_t so = swz((uint32_t)(r * 128 + c * 16));
        size_t go = ((size_t)(bm + r) * K + k0 + c * 8) * 2;
        asm volatile("cp.async.cg.shared.global [%0], [%1], 16;" :: "r"(sb + N_SM_A(s) + so), "l"(A + go) : "memory");
    }
#pragma unroll
    for (int i = 0; i < 4; i++) {
        int idx = tid + i * 128;
        int r = idx >> 3, c = idx & 7;
        uint32_t so = swz((uint32_t)(r * 128 + c * 16));
        size_t go = ((size_t)(bn + r) * K + k0 + c * 8) * 2;
        asm volatile("cp.async.cg.shared.global [%0], [%1], 16;" :: "r"(sb + N_SM_B(s) + so), "l"(B + go) : "memory");
    }
    asm volatile("cp.async.commit_group;" ::: "memory");
}

__global__ void __launch_bounds__(128, 2) gemm_scores(
    const void* A_, const void* B_,
    int K, int KT,
    const float* __restrict__ dec, const float* __restrict__ cov,
    const float* __restrict__ v, float* __restrict__ scores)
{
    extern __shared__ char smem[];
    const uint32_t sb = smem_u32(smem);
    const int tid = threadIdx.x;
    const int wid = tid >> 5, lane = tid & 31;
    const int wm = wid & 1, wn = wid >> 1;
    const int bm = blockIdx.y * 128, bn = blockIdx.x * 64;
    const char* A = (const char*)A_;
    const char* B = (const char*)B_;

    float acc[4][4][4];
#pragma unroll
    for (int a = 0; a < 4; a++)
#pragma unroll
        for (int b = 0; b < 4; b++)
#pragma unroll
            for (int c = 0; c < 4; c++) acc[a][b][c] = 0.f;

    const uint32_t a_row  = (uint32_t)(wm * 64 + (lane & 15));
    const uint32_t a_kofs = (uint32_t)(((lane >> 4) & 1) * 16);
    const uint32_t b_row  = (uint32_t)(wn * 32 + (lane & 7) + ((lane >> 4) & 1) * 8);
    const uint32_t b_kofs = (uint32_t)(((lane >> 3) & 1) * 16);

    issue_stage_n(sb, 0, 0, A, B, K, bm, bn, tid);

    for (int kt = 0; kt < KT; kt++) {
        const int s = kt & 1;
        if (kt + 1 < KT) {
            issue_stage_n(sb, s ^ 1, kt + 1, A, B, K, bm, bn, tid);
            asm volatile("cp.async.wait_group 1;" ::: "memory");
        } else {
            asm volatile("cp.async.wait_group 0;" ::: "memory");
        }
        __syncthreads();

        const uint32_t aS = sb + N_SM_A(s), bS = sb + N_SM_B(s);
#pragma unroll
        for (int kk = 0; kk < 4; kk++) {
            uint32_t fA[4][4], fB[2][4];
#pragma unroll
            for (int mi = 0; mi < 4; mi++) {
                uint32_t off = swz((a_row + mi * 16) * 128 + kk * 32 + a_kofs);
                ldsm4(fA[mi], aS + off);
            }
#pragma unroll
            for (int nq = 0; nq < 2; nq++) {
                uint32_t off = swz((b_row + nq * 16) * 128 + kk * 32 + b_kofs);
                ldsm4(fB[nq], bS + off);
            }
#pragma unroll
            for (int mi = 0; mi < 4; mi++)
#pragma unroll
                for (int nt = 0; nt < 4; nt++)
                    mma_h(acc[mi][nt], fA[mi], &fB[nt >> 1][(nt & 1) * 2]);
        }
        __syncthreads();
    }

    const int g = lane >> 2, tig = lane & 3;
#pragma unroll
    for (int mi = 0; mi < 4; mi++) {
#pragma unroll
        for (int h = 0; h < 2; h++) {
            const int m = bm + wm * 64 + mi * 16 + g + h * 8;
            const float cv = cov[m];
            const int bofs = (m / TK) * DH;
            float rsum = 0.f;
#pragma unroll
            for (int nt = 0; nt < 4; nt++) {
                const int n = bn + wn * 32 + nt * 8 + 2 * tig;
                rsum += tanhf(acc[mi][nt][h * 2 + 0] + dec[bofs + n] + cv) * v[n];
                rsum += tanhf(acc[mi][nt][h * 2 + 1] + dec[bofs + n + 1] + cv) * v[n + 1];
            }
            rsum += __shfl_xor_sync(0xffffffffu, rsum, 1);
            rsum += __shfl_xor_sync(0xffffffffu, rsum, 2);
            if (tig == 0) atomicAdd(&scores[m], rsum);
        }
    }
}

// ============================ conversion kernels ============================
// fp32 -> fp16 single, 4 independent float4 loads per thread (MLP=4).
// n4 must be divisible by 1024 (block covers 1024 float4s).
__global__ void __launch_bounds__(256) csingle_h4(
    const float4* __restrict__ in, __half2* __restrict__ oh, int n4)
{
    const int base = blockIdx.x * 1024 + threadIdx.x;
    float4 x[4];
#pragma unroll
    for (int j = 0; j < 4; j++) x[j] = in[base + j * 256];
#pragma unroll
    for (int j = 0; j < 4; j++) {
        const int i = base + j * 256;
        oh[2 * i]     = __floats2half2_rn(x[j].x, x[j].y);
        oh[2 * i + 1] = __floats2half2_rn(x[j].z, x[j].w);
    }
}

__global__ void __launch_bounds__(256) tconv_h1(
    const float* __restrict__ in, __half* __restrict__ oh, int R, int C)
{
    __shared__ float t[32][33];
    const int bx = blockIdx.x * 32, by = blockIdx.y * 32;
    const int x = threadIdx.x & 31, y = threadIdx.x >> 5;
#pragma unroll
    for (int i = 0; i < 32; i += 8)
        t[y + i][x] = in[(size_t)(by + y + i) * C + bx + x];
    __syncthreads();
#pragma unroll
    for (int i = 0; i < 32; i += 8) {
        float val = t[x][y + i];
        oh[(size_t)(bx + y + i) * R + by + x] = __float2half_rn(val);
    }
}

// ============================ small kernels ============================
__global__ void __launch_bounds__(256) b2_kernel(
    const float* __restrict__ bg, const float* __restrict__ Gs,
    const float* __restrict__ bgs, float* __restrict__ b2)
{
    const int j  = blockIdx.x * 256 + threadIdx.x;
    const int k0 = blockIdx.y * 512;
    float s = 0.f;
#pragma unroll 8
    for (int i = 0; i < 512; i++)
        s += bg[k0 + i] * Gs[(size_t)(k0 + i) * DH + j];
    if (blockIdx.y == 0) s += bgs[j];
    atomicAdd(&b2[j], s);
}

__global__ void __launch_bounds__(256) dec_kernel(
    const float* __restrict__ s_t_hat, const float* __restrict__ Wdec,
    const float* __restrict__ bdec, float* __restrict__ dec)
{
    const int idx = blockIdx.x * 256 + threadIdx.x;
    const int b = idx >> 10, j = idx & (DH - 1);
    float s = bdec[j];
#pragma unroll 8
    for (int k = 0; k < DH; k++) s += s_t_hat[b * DH + k] * Wdec[(size_t)k * DH + j];
    dec[idx] = s;
}

__global__ void __launch_bounds__(256) softmax_kernel(
    const float* __restrict__ scores, const float* __restrict__ cov,
    float* __restrict__ alpha, float* __restrict__ out)
{
    const int b = blockIdx.x, t = threadIdx.x;
    __shared__ float red[8];
    __shared__ float smax, ssum;
    float sv = (t < TK) ? scores[b * TK + t] : -3.4e38f;

    float m = sv;
#pragma unroll
    for (int o = 16; o > 0; o >>= 1) m = fmaxf(m, __shfl_xor_sync(0xffffffffu, m, o));
    if ((t & 31) == 0) red[t >> 5] = m;
    __syncthreads();
    if (t < 8) {
        m = red[t];
#pragma unroll
        for (int o = 4; o > 0; o >>= 1) m = fmaxf(m, __shfl_xor_sync(0xffu, m, o));
        if (t == 0) smax = m;
    }
    __syncthreads();

    float e = (t < TK) ? expf(sv - smax) : 0.f;
    float su = e;
#pragma unroll
    for (int o = 16; o > 0; o >>= 1) su += __shfl_xor_sync(0xffffffffu, su, o);
    if ((t & 31) == 0) red[t >> 5] = su;
    __syncthreads();
    if (t < 8) {
        su = red[t];
#pragma unroll
        for (int o = 4; o > 0; o >>= 1) su += __shfl_xor_sync(0xffu, su, o);
        if (t == 0) ssum = su;
    }
    __syncthreads();

    if (t < TK) {
        const float a = e / ssum;
        alpha[b * TK + t] = a;
        out[OUT_ALPHA + b * TK + t] = a;
        out[OUT_COV + b * TK + t] = cov[b * TK + t] + a;
    }
}

// c_img from fp16 hi/lo reconstruction of g_star; half2-vectorized (2 cols/thread)
__global__ void __launch_bounds__(256) cimg_kernel(
    const __half2* __restrict__ gsH, const __half2* __restrict__ gsL,
    const float* __restrict__ alpha, float* __restrict__ out)
{
    const int b = blockIdx.y;
    const int d2 = blockIdx.x * 256 + threadIdx.x;   // half2 index: 0..DH/2-1
    __shared__ float sal[TK];
    if (threadIdx.x < TK) sal[threadIdx.x] = alpha[b * TK + threadIdx.x];
    __syncthreads();
    float s0 = 0.f, s1 = 0.f;
#pragma unroll 4
    for (int t = 0; t < TK; t++) {
        size_t idx = ((size_t)(b * TK + t)) * (DH / 2) + d2;
        float2 h = __half22float2(gsH[idx]);
        float2 l = __half22float2(gsL[idx]);
        s0 += sal[t] * (h.x + l.x);
        s1 += sal[t] * (h.y + l.y);
    }
    *(float2*)&out[OUT_C + b * DH + 2 * d2] = make_float2(s0, s1);
}

// ============================ launch ============================
extern "C" void kernel_launch(void* const* d_in, const int* in_sizes, int n_in,
                              void* d_out, int out_size)
{
    const float* gf   = (const float*)d_in[0];
    const float* sth  = (const float*)d_in[1];
    const float* cov  = (const float*)d_in[2];
    const float* Wg   = (const float*)d_in[3];
    const float* bg   = (const float*)d_in[4];
    const float* Gs   = (const float*)d_in[5];
    const float* bgs  = (const float*)d_in[6];
    const float* Wgs  = (const float*)d_in[7];
    const float* Wdec = (const float*)d_in[8];
    const float* bdec = (const float*)d_in[9];
    const float* v    = (const float*)d_in[10];
    float* out = (float*)d_out;

    __half *WgF, *GsTF, *W2TF, *gfF, *WgsTF, *gsH, *gsL;
    float *b2p, *decp, *scoresp, *alphap;
    cudaGetSymbolAddress((void**)&WgF, g_WgF);
    cudaGetSymbolAddress((void**)&GsTF, g_GsTF);
    cudaGetSymbolAddress((void**)&W2TF, g_W2TF);
    cudaGetSymbolAddress((void**)&gfF, g_gfF);
    cudaGetSymbolAddress((void**)&WgsTF, g_WgsTF);
    cudaGetSymbolAddress((void**)&gsH, g_gsH);     cudaGetSymbolAddress((void**)&gsL, g_gsL);
    cudaGetSymbolAddress((void**)&b2p, g_b2);      cudaGetSymbolAddress((void**)&decp, g_dec);
    cudaGetSymbolAddress((void**)&scoresp, g_scores);
    cudaGetSymbolAddress((void**)&alphap, g_alpha);

    cudaFuncSetAttribute(gemm_wide,   cudaFuncAttributeMaxDynamicSharedMemorySize, WIDE_SMEM);
    cudaFuncSetAttribute(gemm_scores, cudaFuncAttributeMaxDynamicSharedMemorySize, SCORES_SMEM);

    // Side stream + events (created once; resources, not work)
    static cudaStream_t sideS = nullptr;
    static cudaEvent_t evFork0 = nullptr, evFork1 = nullptr, evJoin = nullptr;
    if (sideS == nullptr) {
        cudaStreamCreateWithFlags(&sideS, cudaStreamNonBlocking);
        cudaEventCreateWithFlags(&evFork0, cudaEventDisableTiming);
        cudaEventCreateWithFlags(&evFork1, cudaEventDisableTiming);
        cudaEventCreateWithFlags(&evJoin, cudaEventDisableTiming);
    }

    // ---- fork 0 at stream start: small side work (low DRAM footprint) ----
    cudaEventRecord(evFork0, 0);
    cudaStreamWaitEvent(sideS, evFork0, 0);
    cudaMemsetAsync(b2p, 0, DH * sizeof(float), sideS);
    cudaMemsetAsync(scoresp, 0, BT * sizeof(float), sideS);
    {   dim3 g(DH / 256, 8);  b2_kernel<<<g, 256, 0, sideS>>>(bg, Gs, bgs, b2p); }
    {   dim3 g(DH / 32, DH / 32);  tconv_h1<<<g, 256, 0, sideS>>>(Wgs, WgsTF, DH, DH); }
    dec_kernel<<<(BATCH * DH) / 256, 256, 0, sideS>>>(sth, Wdec, bdec, decp);

    // ---- main: DRAM-bound conversions (exclusive heavy DRAM use) ----
    // Wg -> fp16 single (MLP-4; GFD*GFD/4 = 4M float4s, divisible by 1024)
    csingle_h4<<<(GFD * GFD / 4) / 1024, 256>>>((const float4*)Wg, (__half2*)WgF, GFD * GFD / 4);
    // Gs -> Gs^T fp16 single
    {   dim3 g(DH / 32, GFD / 32);  tconv_h1<<<g, 256>>>(Gs, GsTF, GFD, DH); }
    // fork 1 AFTER main's conversions: gf conversion overlaps only with compute-bound GEMM1
    cudaEventRecord(evFork1, 0);
    // GEMM1 (wide 1-pass): W2T[DH,GFD] = GsT @ Wg^T -> fp16, ldc=GFD
    {
        dim3 grid(GFD / 128, DH / 128);
        gemm_wide<<<grid, 128, WIDE_SMEM>>>(GsTF, WgF, GFD, GFD / KTILE, 3, GFD,
            nullptr, nullptr, nullptr, W2TF);
    }

    // ---- side: gf conversion hidden under GEMM1 ----
    cudaStreamWaitEvent(sideS, evFork1, 0);
    csingle_h4<<<(BT * GFD / 4) / 1024, 256, 0, sideS>>>((const float4*)gf,
        (__half2*)gfF, BT * GFD / 4);
    cudaEventRecord(evJoin, sideS);

    // ---- main: join, then dependent GEMMs ----
    cudaStreamWaitEvent(0, evJoin, 0);
    // GEMM2 (wide 1-pass): g_star = gf @ W2 + b2 -> fp16 hi/lo, ldc=DH
    {
        dim3 grid(DH / 128, BT / 128);
        gemm_wide<<<grid, 128, WIDE_SMEM>>>(gfF, W2TF, GFD, GFD / KTILE, 1, DH,
            b2p, gsH, gsL, nullptr);
    }
    // GEMM3 (narrow 1-pass, fused): scores = tanh(gsH@Wgs + dec + cov) . v
    {
        dim3 grid(DH / 64, BT / 128);
        gemm_scores<<<grid, 128, SCORES_SMEM>>>(gsH, WgsTF, DH, DH / KTILE,
            decp, cov, v, scoresp);
    }
    // softmax + outputs
    softmax_kernel<<<BATCH, 256>>>(scoresp, cov, alphap, out);
    // context vector (reads fp16 hi/lo, half2-vectorized)
    {   dim3 grid(DH / 512, BATCH);  cimg_kernel<<<grid, 256>>>((const __half2*)gsH, (const __half2*)gsL, alphap, out); }
}